// round 2
// baseline (speedup 1.0000x reference)
#include <cuda_runtime.h>
#include <math.h>

#define BB 4
#define CC 128
#define HH 128
#define WW 128
#define HWH (HH*WW)          // 16384
#define NPIX (BB*HWH)        // 65536
#define INNER 512
#define NKV 1024
#define NP 1536              // per-pixel: q(512, pre-scaled) | k(512) | v(512)
#define BLKSZ 8
#define HALO 3
#define KW 14
#define JWIN 196
#define NHEADS 8
#define DH 64
#define NB 256
#define MAXNEG -3.402823466e38f

// scratch (no cudaMalloc allowed)
__device__ float g_P[(size_t)NPIX * NP];
__device__ float g_AO[(size_t)NPIX * INNER];

// ---------------------------------------------------------------------------
// Kernel 1: P[p, :] = x_pixel[p, :] @ [Wq*scale | Wkv]
// grid (1024, 12), block 256. Tile: 64 pixels x 128 cols, K=128 (full).
// ---------------------------------------------------------------------------
__global__ void k_proj(const float* __restrict__ x,
                       const float* __restrict__ Wq,
                       const float* __restrict__ Wkv) {
    extern __shared__ float sm[];
    float* As = sm;              // [128][64]  (k-major)
    float* Bs = sm + 128 * 64;   // [128][128]

    const int t  = threadIdx.x;
    const int p0 = blockIdx.x * 64;
    const int b  = p0 >> 14;
    const int rem = p0 & (HWH - 1);
    const int y  = rem >> 7;
    const int x0 = rem & 127;
    const int jt = blockIdx.y;   // 0..3 -> Wq, 4..11 -> Wkv

    const float* xrow = x + ((size_t)(b * CC) * HH + y) * WW + x0;
    // A tile: vectorized, 128*16 float4 loads
    for (int idx = t; idx < 128 * 16; idx += 256) {
        int k = idx >> 4, i4 = (idx & 15) * 4;
        float4 v = *(const float4*)&xrow[(size_t)k * HWH + i4];
        *(float4*)&As[k * 64 + i4] = v;
    }
    if (jt < 4) {
        const int cb = jt * 128;
        for (int idx = t; idx < 128 * 32; idx += 256) {
            int k = idx >> 5, j4 = (idx & 31) * 4;
            float4 v = *(const float4*)&Wq[k * INNER + cb + j4];
            v.x *= 0.125f; v.y *= 0.125f; v.z *= 0.125f; v.w *= 0.125f;
            *(float4*)&Bs[k * 128 + j4] = v;
        }
    } else {
        const int cb = (jt - 4) * 128;
        for (int idx = t; idx < 128 * 32; idx += 256) {
            int k = idx >> 5, j4 = (idx & 31) * 4;
            *(float4*)&Bs[k * 128 + j4] = *(const float4*)&Wkv[k * NKV + cb + j4];
        }
    }
    __syncthreads();

    const int tx = t & 15, ty = t >> 4;
    float acc[4][8];
    #pragma unroll
    for (int r = 0; r < 4; r++)
        #pragma unroll
        for (int c = 0; c < 8; c++) acc[r][c] = 0.f;

    #pragma unroll 4
    for (int k = 0; k < 128; k++) {
        float a[4], bb[8];
        #pragma unroll
        for (int r = 0; r < 4; r++) a[r] = As[k * 64 + ty + 16 * r];
        #pragma unroll
        for (int c = 0; c < 8; c++) bb[c] = Bs[k * 128 + tx + 16 * c];
        #pragma unroll
        for (int r = 0; r < 4; r++)
            #pragma unroll
            for (int c = 0; c < 8; c++) acc[r][c] += a[r] * bb[c];
    }

    const int gcolb = jt * 128;
    #pragma unroll
    for (int r = 0; r < 4; r++) {
        int p = p0 + ty + 16 * r;
        float* dst = g_P + (size_t)p * NP + gcolb;
        #pragma unroll
        for (int c = 0; c < 8; c++) dst[tx + 16 * c] = acc[r][c];
    }
}

// ---------------------------------------------------------------------------
// Kernel 2: halo attention per (nb, head, b). block 256.
// smem: qs[64][68] + ks[196][68] + vs[196][68] + ss[64][200] = 175232 B
// ---------------------------------------------------------------------------
__global__ void k_attn() {
    extern __shared__ float sm[];
    float* qs = sm;                         // 64*68
    float* ks = qs + 64 * 68;               // 196*68
    float* vs = ks + 196 * 68;              // 196*68
    float* ss = vs + 196 * 68;              // 64*200 (col 196 holds 1/sum)

    const int t    = threadIdx.x;
    const int nb   = blockIdx.x;
    const int head = blockIdx.y;
    const int b    = blockIdx.z;
    const int by   = nb >> 4, bx = nb & 15;
    const int qoff = head * DH;
    const int pbase = b * HWH;

    // load q rows (pre-scaled), float4
    for (int idx = t; idx < 64 * 16; idx += 256) {
        int i = idx >> 4, d4 = (idx & 15) * 4;
        int gy = by * 8 + (i >> 3), gx = bx * 8 + (i & 7);
        float4 v = *(const float4*)&g_P[(size_t)(pbase + gy * 128 + gx) * NP + qoff + d4];
        *(float4*)&qs[i * 68 + d4] = v;
    }
    // gather k, v halo window (out-of-bounds -> 0, masked later), float4
    for (int idx = t; idx < JWIN * 16; idx += 256) {
        int j = idx >> 4, d4 = (idx & 15) * 4;
        int wy = j / 14, wx = j % 14;
        int gy = by * 8 - 3 + wy, gx = bx * 8 - 3 + wx;
        bool valid = ((unsigned)gy < 128u) && ((unsigned)gx < 128u);
        float4 kv0 = make_float4(0.f, 0.f, 0.f, 0.f);
        float4 kv1 = kv0;
        if (valid) {
            size_t base = (size_t)(pbase + gy * 128 + gx) * NP + 512 + qoff + d4;
            kv0 = *(const float4*)&g_P[base];
            kv1 = *(const float4*)&g_P[base + 512];
        }
        *(float4*)&ks[j * 68 + d4] = kv0;
        *(float4*)&vs[j * 68 + d4] = kv1;
    }
    __syncthreads();

    // S = q @ k^T  : thread = 4 rows x 13 cols
    const int rg = t >> 4, cj = t & 15;
    const int i0 = rg * 4;
    float acc[4][13];
    #pragma unroll
    for (int r = 0; r < 4; r++)
        #pragma unroll
        for (int jj = 0; jj < 13; jj++) acc[r][jj] = 0.f;

    #pragma unroll 2
    for (int d = 0; d < 64; d++) {
        float a[4];
        #pragma unroll
        for (int r = 0; r < 4; r++) a[r] = qs[(i0 + r) * 68 + d];
        #pragma unroll
        for (int jj = 0; jj < 13; jj++) {
            int j = cj * 13 + jj;
            int jc = j < 196 ? j : 195;            // clamp: OOB lanes discarded at store
            float kk = ks[jc * 68 + d];
            #pragma unroll
            for (int r = 0; r < 4; r++) acc[r][jj] += a[r] * kk;
        }
    }
    #pragma unroll
    for (int jj = 0; jj < 13; jj++) {
        int j = cj * 13 + jj;
        if (j < 196) {
            int wy = j / 14, wx = j % 14;
            int gy = by * 8 - 3 + wy, gx = bx * 8 - 3 + wx;
            bool valid = ((unsigned)gy < 128u) && ((unsigned)gx < 128u);
            #pragma unroll
            for (int r = 0; r < 4; r++)
                ss[(i0 + r) * 200 + j] = valid ? acc[r][jj] : MAXNEG;
        }
    }
    __syncthreads();

    // softmax per row: 4 lanes per row
    {
        const int i = t >> 2, part = t & 3;
        float m = MAXNEG;
        for (int jj = part; jj < 196; jj += 4) m = fmaxf(m, ss[i * 200 + jj]);
        m = fmaxf(m, __shfl_xor_sync(0xffffffffu, m, 1));
        m = fmaxf(m, __shfl_xor_sync(0xffffffffu, m, 2));
        float sum = 0.f;
        for (int jj = part; jj < 196; jj += 4) {
            float e = __expf(ss[i * 200 + jj] - m);
            ss[i * 200 + jj] = e;
            sum += e;
        }
        sum += __shfl_xor_sync(0xffffffffu, sum, 1);
        sum += __shfl_xor_sync(0xffffffffu, sum, 2);
        if (part == 0) ss[i * 200 + 196] = 1.0f / sum;
    }
    __syncthreads();

    // O = attn @ v : thread = 4 rows x 4 cols (float4 on v)
    const int dc = t & 15;
    const int d0 = dc * 4;
    float o[4][4];
    #pragma unroll
    for (int r = 0; r < 4; r++)
        #pragma unroll
        for (int m2 = 0; m2 < 4; m2++) o[r][m2] = 0.f;

    #pragma unroll 2
    for (int j = 0; j < 196; j++) {
        float4 v4 = *(const float4*)&vs[j * 68 + d0];
        #pragma unroll
        for (int r = 0; r < 4; r++) {
            float s = ss[(i0 + r) * 200 + j];
            o[r][0] += s * v4.x;
            o[r][1] += s * v4.y;
            o[r][2] += s * v4.z;
            o[r][3] += s * v4.w;
        }
    }
    #pragma unroll
    for (int r = 0; r < 4; r++) {
        float inv = ss[(i0 + r) * 200 + 196];
        int i = i0 + r;
        int gy = by * 8 + (i >> 3), gx = bx * 8 + (i & 7);
        float4 res;
        res.x = o[r][0] * inv; res.y = o[r][1] * inv;
        res.z = o[r][2] * inv; res.w = o[r][3] * inv;
        *(float4*)&g_AO[(size_t)(pbase + gy * 128 + gx) * INNER + qoff + d0] = res;
    }
}

// ---------------------------------------------------------------------------
// Kernel 3: out[b,c,y,x] = AO[p,:] @ Wo + bo  (K=512 in 4 chunks of 128)
// ---------------------------------------------------------------------------
__global__ void k_out(const float* __restrict__ Wo,
                      const float* __restrict__ bo,
                      float* __restrict__ out) {
    extern __shared__ float sm[];
    float* As = sm;              // [64][132] i-major, padded (132 for float4+skew)
    float* Bs = sm + 64 * 132;   // [128][128]

    const int t  = threadIdx.x;
    const int tx = t & 15, ty = t >> 4;
    const int p0 = blockIdx.x * 64;

    float acc[4][8];
    #pragma unroll
    for (int r = 0; r < 4; r++)
        #pragma unroll
        for (int c = 0; c < 8; c++) acc[r][c] = 0.f;

    for (int kc = 0; kc < 4; kc++) {
        const int K0 = kc * 128;
        __syncthreads();
        for (int idx = t; idx < 64 * 32; idx += 256) {
            int i = idx >> 5, k4 = (idx & 31) * 4;
            *(float4*)&As[i * 132 + k4] =
                *(const float4*)&g_AO[(size_t)(p0 + i) * INNER + K0 + k4];
        }
        for (int idx = t; idx < 128 * 32; idx += 256) {
            int k = idx >> 5, c4 = (idx & 31) * 4;
            *(float4*)&Bs[k * 128 + c4] = *(const float4*)&Wo[(K0 + k) * CC + c4];
        }
        __syncthreads();

        #pragma unroll 4
        for (int k = 0; k < 128; k++) {
            float a[4], bb[8];
            #pragma unroll
            for (int r = 0; r < 4; r++) a[r] = As[(ty + 16 * r) * 132 + k];
            #pragma unroll
            for (int c = 0; c < 8; c++) bb[c] = Bs[k * 128 + tx + 16 * c];
            #pragma unroll
            for (int r = 0; r < 4; r++)
                #pragma unroll
                for (int c = 0; c < 8; c++) acc[r][c] += a[r] * bb[c];
        }
    }

    const int b = p0 >> 14, rem = p0 & (HWH - 1);
    const int y = rem >> 7, x0 = rem & 127;
    #pragma unroll
    for (int r = 0; r < 4; r++) {
        int i = ty + 16 * r;
        #pragma unroll
        for (int c = 0; c < 8; c++) {
            int ccol = tx + 16 * c;
            out[((size_t)(b * CC + ccol) * HH + y) * WW + x0 + i] = acc[r][c] + bo[ccol];
        }
    }
}

extern "C" void kernel_launch(void* const* d_in, const int* in_sizes, int n_in,
                              void* d_out, int out_size) {
    const float* x   = (const float*)d_in[0];
    const float* Wq  = (const float*)d_in[1];
    const float* Wkv = (const float*)d_in[2];
    const float* Wo  = (const float*)d_in[3];
    const float* bo  = (const float*)d_in[4];
    float* out = (float*)d_out;

    const int smem1 = (128 * 64 + 128 * 128) * 4;              // 98304
    const int smem2 = (64 * 68 + 196 * 68 * 2 + 64 * 200) * 4; // 175232
    const int smem3 = (64 * 132 + 128 * 128) * 4;              // 99328

    cudaFuncSetAttribute(k_proj, cudaFuncAttributeMaxDynamicSharedMemorySize, smem1);
    cudaFuncSetAttribute(k_attn, cudaFuncAttributeMaxDynamicSharedMemorySize, smem2);
    cudaFuncSetAttribute(k_out,  cudaFuncAttributeMaxDynamicSharedMemorySize, smem3);

    dim3 g1(NPIX / 64, 12);
    k_proj<<<g1, 256, smem1>>>(x, Wq, Wkv);

    dim3 g2(NB, NHEADS, BB);
    k_attn<<<g2, 256, smem2>>>();

    dim3 g3(NPIX / 64);
    k_out<<<g3, 256, smem3>>>(Wo, bo, out);
}

// round 4
// speedup vs baseline: 2.0194x; 2.0194x over previous
#include <cuda_runtime.h>
#include <stdint.h>
#include <math.h>

#define BB 4
#define CC 128
#define HWH 16384
#define NPIX 65536
#define INNER 512
#define NP 1536
#define MAXNEG -3.402823466e38f

// scratch (no cudaMalloc allowed)
__device__ float g_P[(size_t)NPIX * NP];      // per-pixel [q(512, pre-scaled) | k(512) | v(512)]
__device__ float g_AO[(size_t)NPIX * INNER];

__device__ __forceinline__ uint32_t f2tf(float f) {
    uint32_t u; asm("cvt.rna.tf32.f32 %0, %1;" : "=r"(u) : "f"(f)); return u;
}
__device__ __forceinline__ float f2tff(float f) { return __uint_as_float(f2tf(f)); }

__device__ __forceinline__ void mma8(float* c,
                                     uint32_t a0, uint32_t a1, uint32_t a2, uint32_t a3,
                                     uint32_t b0, uint32_t b1) {
    asm volatile("mma.sync.aligned.m16n8k8.row.col.f32.tf32.tf32.f32 "
        "{%0,%1,%2,%3}, {%4,%5,%6,%7}, {%8,%9}, {%0,%1,%2,%3};"
        : "+f"(c[0]), "+f"(c[1]), "+f"(c[2]), "+f"(c[3])
        : "r"(a0), "r"(a1), "r"(a2), "r"(a3), "r"(b0), "r"(b1));
}

// ---------------------------------------------------------------------------
// Kernel 1: P[p,:] = x_pixel[p,:] @ [Wq*0.125 | Wkv].  TF32 MMA.
// grid (12, 512): blockIdx.x = col tile (128), blockIdx.y = pixel tile (128 = one row).
// block 256 = 8 warps (2m x 4n), warp tile 64x32. K=128 in 2 chunks of 64.
// smem: As[64][132] (k-major, tf32) + Bs[64][132]
// ---------------------------------------------------------------------------
__global__ void __launch_bounds__(256) k_proj(const float* __restrict__ x,
                                              const float* __restrict__ Wq,
                                              const float* __restrict__ Wkv) {
    extern __shared__ float sm[];
    float* As = sm;              // [k=64][m=128 +4 pad]
    float* Bs = sm + 64 * 132;   // [k=64][n=128 +4 pad]

    const int t = threadIdx.x, w = t >> 5, lane = t & 31;
    const int g = lane >> 2, tq = lane & 3;
    const int m0w = (w & 1) * 64, n0w = (w >> 1) * 32;
    const int jt = blockIdx.x;                 // 0..3 Wq, 4..11 Wkv
    const int p0 = blockIdx.y * 128;
    const int b  = p0 >> 14;
    const int y  = (p0 & (HWH - 1)) >> 7;

    float acc[4][4][4];
    #pragma unroll
    for (int mt = 0; mt < 4; mt++)
        #pragma unroll
        for (int nt = 0; nt < 4; nt++)
            #pragma unroll
            for (int e = 0; e < 4; e++) acc[mt][nt][e] = 0.f;

    for (int kc = 0; kc < 2; kc++) {
        const int K0 = kc * 64;
        __syncthreads();
        const float* xb = x + ((size_t)(b * CC + K0) * 128 + y) * 128;
        for (int idx = t; idx < 64 * 32; idx += 256) {
            int k = idx >> 5, m4 = (idx & 31) * 4;
            float4 v = *(const float4*)(xb + (size_t)k * HWH + m4);
            float* d = &As[k * 132 + m4];
            d[0] = f2tff(v.x); d[1] = f2tff(v.y); d[2] = f2tff(v.z); d[3] = f2tff(v.w);
        }
        if (jt < 4) {
            const float* Wb = Wq + (size_t)K0 * INNER + jt * 128;
            for (int idx = t; idx < 64 * 32; idx += 256) {
                int k = idx >> 5, n4 = (idx & 31) * 4;
                float4 v = *(const float4*)(Wb + (size_t)k * INNER + n4);
                float* d = &Bs[k * 132 + n4];
                d[0] = f2tff(v.x * 0.125f); d[1] = f2tff(v.y * 0.125f);
                d[2] = f2tff(v.z * 0.125f); d[3] = f2tff(v.w * 0.125f);
            }
        } else {
            const float* Wb = Wkv + (size_t)K0 * 1024 + (jt - 4) * 128;
            for (int idx = t; idx < 64 * 32; idx += 256) {
                int k = idx >> 5, n4 = (idx & 31) * 4;
                float4 v = *(const float4*)(Wb + (size_t)k * 1024 + n4);
                float* d = &Bs[k * 132 + n4];
                d[0] = f2tff(v.x); d[1] = f2tff(v.y); d[2] = f2tff(v.z); d[3] = f2tff(v.w);
            }
        }
        __syncthreads();

        #pragma unroll
        for (int ks = 0; ks < 8; ks++) {
            const int k0 = ks * 8;
            uint32_t af[4][4];
            #pragma unroll
            for (int mt = 0; mt < 4; mt++) {
                int m = m0w + mt * 16 + g;
                af[mt][0] = __float_as_uint(As[(k0 + tq) * 132 + m]);
                af[mt][1] = __float_as_uint(As[(k0 + tq) * 132 + m + 8]);
                af[mt][2] = __float_as_uint(As[(k0 + tq + 4) * 132 + m]);
                af[mt][3] = __float_as_uint(As[(k0 + tq + 4) * 132 + m + 8]);
            }
            #pragma unroll
            for (int nt = 0; nt < 4; nt++) {
                int n = n0w + nt * 8 + g;
                uint32_t b0 = __float_as_uint(Bs[(k0 + tq) * 132 + n]);
                uint32_t b1 = __float_as_uint(Bs[(k0 + tq + 4) * 132 + n]);
                #pragma unroll
                for (int mt = 0; mt < 4; mt++)
                    mma8(acc[mt][nt], af[mt][0], af[mt][1], af[mt][2], af[mt][3], b0, b1);
            }
        }
    }

    const int colb = jt * 128;
    #pragma unroll
    for (int mt = 0; mt < 4; mt++) {
        int m = m0w + mt * 16 + g;
        #pragma unroll
        for (int nt = 0; nt < 4; nt++) {
            int n = colb + n0w + nt * 8 + tq * 2;
            float2 v0 = make_float2(acc[mt][nt][0], acc[mt][nt][1]);
            float2 v1 = make_float2(acc[mt][nt][2], acc[mt][nt][3]);
            *(float2*)&g_P[(size_t)(p0 + m) * NP + n]     = v0;
            *(float2*)&g_P[(size_t)(p0 + m + 8) * NP + n] = v1;
        }
    }
}

// ---------------------------------------------------------------------------
// Kernel 2: halo attention per (nb, head, b). 256 threads, TF32 MMA.
// S: M=64, N=196 (pad 208), K=64. O: M=64, N=64, K=200 (196 + 4 zero rows).
// smem: qs[64][68] ks[208][68] vs[200][68] ss[64][212]
// ---------------------------------------------------------------------------
__global__ void __launch_bounds__(256) k_attn() {
    extern __shared__ float sm[];
    float* qs = sm;                     // 64*68
    float* ks = qs + 64 * 68;           // 208*68 (rows 196..207 never read unmasked)
    float* vs = ks + 208 * 68;          // 200*68 (rows 196..199 zeroed)
    float* ss = vs + 200 * 68;          // 64*212 (cols 0..199 attn, col 210 = 1/sum)

    const int t = threadIdx.x, w = t >> 5, lane = t & 31;
    const int g = lane >> 2, tq = lane & 3;
    const int nb   = blockIdx.x;
    const int head = blockIdx.y;
    const int b    = blockIdx.z;
    const int by = nb >> 4, bx = nb & 15;
    const int qoff = head * 64;
    const int pbase = b * HWH;

    // ---- gather q (pre-scaled), convert tf32 ----
    for (int idx = t; idx < 64 * 16; idx += 256) {
        int i = idx >> 4, d4 = (idx & 15) * 4;
        int gy = by * 8 + (i >> 3), gx = bx * 8 + (i & 7);
        float4 v = *(const float4*)&g_P[(size_t)(pbase + gy * 128 + gx) * NP + qoff + d4];
        float* d = &qs[i * 68 + d4];
        d[0] = f2tff(v.x); d[1] = f2tff(v.y); d[2] = f2tff(v.z); d[3] = f2tff(v.w);
    }
    // ---- gather k, v halo windows ----
    for (int idx = t; idx < 196 * 16; idx += 256) {
        int j = idx >> 4, d4 = (idx & 15) * 4;
        int wy = j / 14, wx = j % 14;
        int gy = by * 8 - 3 + wy, gx = bx * 8 - 3 + wx;
        bool valid = ((unsigned)gy < 128u) && ((unsigned)gx < 128u);
        float4 kv0 = make_float4(0.f, 0.f, 0.f, 0.f), kv1 = kv0;
        if (valid) {
            size_t base = (size_t)(pbase + gy * 128 + gx) * NP + 512 + qoff + d4;
            kv0 = *(const float4*)&g_P[base];
            kv1 = *(const float4*)&g_P[base + 512];
        }
        float* dk = &ks[j * 68 + d4];
        dk[0] = f2tff(kv0.x); dk[1] = f2tff(kv0.y); dk[2] = f2tff(kv0.z); dk[3] = f2tff(kv0.w);
        float* dv = &vs[j * 68 + d4];
        dv[0] = f2tff(kv1.x); dv[1] = f2tff(kv1.y); dv[2] = f2tff(kv1.z); dv[3] = f2tff(kv1.w);
    }
    // zero pad rows of vs (196..199) and ks (196..207)
    for (int idx = t; idx < 4 * 68; idx += 256) vs[(196 + idx / 68) * 68 + (idx % 68)] = 0.f;
    for (int idx = t; idx < 12 * 68; idx += 256) ks[(196 + idx / 68) * 68 + (idx % 68)] = 0.f;
    __syncthreads();

    // ---- S = q @ k^T : warp w -> m-tile (w&3), n-half (w>>2), 13 n-tiles ----
    const int m0 = (w & 3) * 16;
    {
        const int n0h = (w >> 2) * 104;
        float sacc[13][4];
        #pragma unroll
        for (int nt = 0; nt < 13; nt++)
            #pragma unroll
            for (int e = 0; e < 4; e++) sacc[nt][e] = 0.f;

        #pragma unroll
        for (int ks8 = 0; ks8 < 8; ks8++) {
            const int k0 = ks8 * 8;
            uint32_t a0 = __float_as_uint(qs[(m0 + g) * 68 + k0 + tq]);
            uint32_t a1 = __float_as_uint(qs[(m0 + g + 8) * 68 + k0 + tq]);
            uint32_t a2 = __float_as_uint(qs[(m0 + g) * 68 + k0 + tq + 4]);
            uint32_t a3 = __float_as_uint(qs[(m0 + g + 8) * 68 + k0 + tq + 4]);
            #pragma unroll
            for (int nt = 0; nt < 13; nt++) {
                int n = n0h + nt * 8 + g;
                uint32_t b0 = __float_as_uint(ks[n * 68 + k0 + tq]);
                uint32_t b1 = __float_as_uint(ks[n * 68 + k0 + tq + 4]);
                mma8(sacc[nt], a0, a1, a2, a3, b0, b1);
            }
        }
        // store with mask
        #pragma unroll
        for (int nt = 0; nt < 13; nt++) {
            int j0 = n0h + nt * 8;
            int jA = j0 + tq * 2, jB = jA + 1;
            int rA = m0 + g, rB = rA + 8;
            if (jA < 200) {
                bool vA = false;
                if (jA < 196) {
                    int wy = jA / 14, wx = jA % 14;
                    int gy = by * 8 - 3 + wy, gx = bx * 8 - 3 + wx;
                    vA = ((unsigned)gy < 128u) && ((unsigned)gx < 128u);
                }
                ss[rA * 212 + jA] = vA ? sacc[nt][0] : MAXNEG;
                ss[rB * 212 + jA] = vA ? sacc[nt][2] : MAXNEG;
            }
            if (jB < 200) {
                bool vB = false;
                if (jB < 196) {
                    int wy = jB / 14, wx = jB % 14;
                    int gy = by * 8 - 3 + wy, gx = bx * 8 - 3 + wx;
                    vB = ((unsigned)gy < 128u) && ((unsigned)gx < 128u);
                }
                ss[rA * 212 + jB] = vB ? sacc[nt][1] : MAXNEG;
                ss[rB * 212 + jB] = vB ? sacc[nt][3] : MAXNEG;
            }
        }
    }
    __syncthreads();

    // ---- softmax: 4 lanes per row over 200 cols; exp stored as tf32 ----
    {
        const int i = t >> 2, part = t & 3;
        float* row = &ss[i * 212];
        float m = MAXNEG;
        for (int jj = part; jj < 200; jj += 4) m = fmaxf(m, row[jj]);
        m = fmaxf(m, __shfl_xor_sync(0xffffffffu, m, 1));
        m = fmaxf(m, __shfl_xor_sync(0xffffffffu, m, 2));
        float sum = 0.f;
        for (int jj = part; jj < 200; jj += 4) {
            float e = __expf(row[jj] - m);
            sum += e;
            row[jj] = f2tff(e);
        }
        sum += __shfl_xor_sync(0xffffffffu, sum, 1);
        sum += __shfl_xor_sync(0xffffffffu, sum, 2);
        if (part == 0) row[210] = 1.0f / sum;
    }
    __syncthreads();

    // ---- O = attn @ v : warp w -> m-tile (w&3), n cols (w>>2)*32, 4 n-tiles ----
    {
        const int n0w = (w >> 2) * 32;
        float oacc[4][4];
        #pragma unroll
        for (int nt = 0; nt < 4; nt++)
            #pragma unroll
            for (int e = 0; e < 4; e++) oacc[nt][e] = 0.f;

        for (int ks8 = 0; ks8 < 25; ks8++) {
            const int k0 = ks8 * 8;
            uint32_t a0 = __float_as_uint(ss[(m0 + g) * 212 + k0 + tq]);
            uint32_t a1 = __float_as_uint(ss[(m0 + g + 8) * 212 + k0 + tq]);
            uint32_t a2 = __float_as_uint(ss[(m0 + g) * 212 + k0 + tq + 4]);
            uint32_t a3 = __float_as_uint(ss[(m0 + g + 8) * 212 + k0 + tq + 4]);
            #pragma unroll
            for (int nt = 0; nt < 4; nt++) {
                int n = n0w + nt * 8 + g;
                uint32_t b0 = __float_as_uint(vs[(k0 + tq) * 68 + n]);
                uint32_t b1 = __float_as_uint(vs[(k0 + tq + 4) * 68 + n]);
                mma8(oacc[nt], a0, a1, a2, a3, b0, b1);
            }
        }
        // epilogue: normalize + scatter to g_AO
        const int rA = m0 + g, rB = rA + 8;
        const float invA = ss[rA * 212 + 210];
        const float invB = ss[rB * 212 + 210];
        const int gyA = by * 8 + (rA >> 3), gxA = bx * 8 + (rA & 7);
        const int gyB = by * 8 + (rB >> 3), gxB = bx * 8 + (rB & 7);
        float* dstA = &g_AO[(size_t)(pbase + gyA * 128 + gxA) * INNER + qoff];
        float* dstB = &g_AO[(size_t)(pbase + gyB * 128 + gxB) * INNER + qoff];
        #pragma unroll
        for (int nt = 0; nt < 4; nt++) {
            int n = n0w + nt * 8 + tq * 2;
            *(float2*)&dstA[n] = make_float2(oacc[nt][0] * invA, oacc[nt][1] * invA);
            *(float2*)&dstB[n] = make_float2(oacc[nt][2] * invB, oacc[nt][3] * invB);
        }
    }
}

// ---------------------------------------------------------------------------
// Kernel 3: out = AO @ Wo + bo, transposed store. TF32 MMA.
// grid 512 (128 pixels = one image row), block 256 = 8 warps (2m x 4n).
// K=512 in 8 chunks of 64. smem: As[128][68] (row-major) + Bs[64][132]
// ---------------------------------------------------------------------------
__global__ void __launch_bounds__(256) k_out(const float* __restrict__ Wo,
                                             const float* __restrict__ bo,
                                             float* __restrict__ out) {
    extern __shared__ float sm[];
    float* As = sm;              // [m=128][k=64 +4 pad]
    float* Bs = sm + 128 * 68;   // [k=64][n=128 +4 pad]

    const int t = threadIdx.x, w = t >> 5, lane = t & 31;
    const int g = lane >> 2, tq = lane & 3;
    const int m0w = (w & 1) * 64, n0w = (w >> 1) * 32;
    const int p0 = blockIdx.x * 128;
    const int b  = p0 >> 14;
    const int y  = (p0 & (HWH - 1)) >> 7;

    float acc[4][4][4];
    #pragma unroll
    for (int mt = 0; mt < 4; mt++)
        #pragma unroll
        for (int nt = 0; nt < 4; nt++)
            #pragma unroll
            for (int e = 0; e < 4; e++) acc[mt][nt][e] = 0.f;

    for (int kc = 0; kc < 8; kc++) {
        const int K0 = kc * 64;
        __syncthreads();
        for (int idx = t; idx < 128 * 16; idx += 256) {
            int m = idx >> 4, k4 = (idx & 15) * 4;
            float4 v = *(const float4*)&g_AO[(size_t)(p0 + m) * INNER + K0 + k4];
            float* d = &As[m * 68 + k4];
            d[0] = f2tff(v.x); d[1] = f2tff(v.y); d[2] = f2tff(v.z); d[3] = f2tff(v.w);
        }
        for (int idx = t; idx < 64 * 32; idx += 256) {
            int k = idx >> 5, n4 = (idx & 31) * 4;
            float4 v = *(const float4*)&Wo[(size_t)(K0 + k) * CC + n4];
            float* d = &Bs[k * 132 + n4];
            d[0] = f2tff(v.x); d[1] = f2tff(v.y); d[2] = f2tff(v.z); d[3] = f2tff(v.w);
        }
        __syncthreads();

        #pragma unroll
        for (int ks8 = 0; ks8 < 8; ks8++) {
            const int k0 = ks8 * 8;
            uint32_t af[4][4];
            #pragma unroll
            for (int mt = 0; mt < 4; mt++) {
                int m = m0w + mt * 16 + g;
                af[mt][0] = __float_as_uint(As[m * 68 + k0 + tq]);
                af[mt][1] = __float_as_uint(As[(m + 8) * 68 + k0 + tq]);
                af[mt][2] = __float_as_uint(As[m * 68 + k0 + tq + 4]);
                af[mt][3] = __float_as_uint(As[(m + 8) * 68 + k0 + tq + 4]);
            }
            #pragma unroll
            for (int nt = 0; nt < 4; nt++) {
                int n = n0w + nt * 8 + g;
                uint32_t b0 = __float_as_uint(Bs[(k0 + tq) * 132 + n]);
                uint32_t b1 = __float_as_uint(Bs[(k0 + tq + 4) * 132 + n]);
                #pragma unroll
                for (int mt = 0; mt < 4; mt++)
                    mma8(acc[mt][nt], af[mt][0], af[mt][1], af[mt][2], af[mt][3], b0, b1);
            }
        }
    }

    // epilogue: out[b][n][y][m] = acc + bo[n]
    #pragma unroll
    for (int nt = 0; nt < 4; nt++) {
        int nA = n0w + nt * 8 + tq * 2, nB = nA + 1;
        float biasA = bo[nA], biasB = bo[nB];
        float* colA = out + (size_t)(b * CC + nA) * HWH + y * 128;
        float* colB = out + (size_t)(b * CC + nB) * HWH + y * 128;
        #pragma unroll
        for (int mt = 0; mt < 4; mt++) {
            int m = m0w + mt * 16 + g;
            colA[m]     = acc[mt][nt][0] + biasA;
            colB[m]     = acc[mt][nt][1] + biasB;
            colA[m + 8] = acc[mt][nt][2] + biasA;
            colB[m + 8] = acc[mt][nt][3] + biasB;
        }
    }
}

extern "C" void kernel_launch(void* const* d_in, const int* in_sizes, int n_in,
                              void* d_out, int out_size) {
    const float* x   = (const float*)d_in[0];
    const float* Wq  = (const float*)d_in[1];
    const float* Wkv = (const float*)d_in[2];
    const float* Wo  = (const float*)d_in[3];
    const float* bo  = (const float*)d_in[4];
    float* out = (float*)d_out;

    const int smem1 = 2 * 64 * 132 * 4;                               // 67584
    const int smem2 = (64 * 68 + 208 * 68 + 200 * 68 + 64 * 212) * 4; // 182656
    const int smem3 = (128 * 68 + 64 * 132) * 4;                      // 68608

    cudaFuncSetAttribute(k_proj, cudaFuncAttributeMaxDynamicSharedMemorySize, smem1);
    cudaFuncSetAttribute(k_attn, cudaFuncAttributeMaxDynamicSharedMemorySize, smem2);
    cudaFuncSetAttribute(k_out,  cudaFuncAttributeMaxDynamicSharedMemorySize, smem3);

    dim3 g1(12, 512);
    k_proj<<<g1, 256, smem1>>>(x, Wq, Wkv);

    dim3 g2(256, 8, 4);
    k_attn<<<g2, 256, smem2>>>();

    dim3 g3(512);
    k_out<<<g3, 256, smem3>>>(Wo, bo, out);
}

// round 5
// speedup vs baseline: 2.6604x; 1.3175x over previous
#include <cuda_runtime.h>
#include <stdint.h>
#include <math.h>

#define BB 4
#define CC 128
#define HWH 16384
#define NPIX 65536
#define INNER 512
#define NP 1536
#define MAXNEG -3.402823466e38f

__device__ float g_P[(size_t)NPIX * NP];      // per-pixel [q(512, pre-scaled) | k(512) | v(512)]
__device__ float g_AO[(size_t)NPIX * INNER];

__device__ __forceinline__ uint32_t f2tf(float f) {
    uint32_t u; asm("cvt.rna.tf32.f32 %0, %1;" : "=r"(u) : "f"(f)); return u;
}
__device__ __forceinline__ float f2tff(float f) { return __uint_as_float(f2tf(f)); }

__device__ __forceinline__ void mma8(float* c,
                                     uint32_t a0, uint32_t a1, uint32_t a2, uint32_t a3,
                                     uint32_t b0, uint32_t b1) {
    asm volatile("mma.sync.aligned.m16n8k8.row.col.f32.tf32.tf32.f32 "
        "{%0,%1,%2,%3}, {%4,%5,%6,%7}, {%8,%9}, {%0,%1,%2,%3};"
        : "+f"(c[0]), "+f"(c[1]), "+f"(c[2]), "+f"(c[3])
        : "r"(a0), "r"(a1), "r"(a2), "r"(a3), "r"(b0), "r"(b1));
}

// ---------------------------------------------------------------------------
// Kernel 1: P[p,:] = x_pixel[p,:] @ [Wq*0.125 | Wkv].  TF32 MMA.
// grid (12, 512), block 256 = 8 warps (2m x 4n), warp tile 64x32. K=128 (2x64).
// Strides 136 (== 8 mod 32): conflict-free A/B fragment loads.
// ---------------------------------------------------------------------------
#define S1 136
__global__ void __launch_bounds__(256) k_proj(const float* __restrict__ x,
                                              const float* __restrict__ Wq,
                                              const float* __restrict__ Wkv) {
    extern __shared__ float sm[];
    float* As = sm;              // [k=64][m=128 pad->136]
    float* Bs = sm + 64 * S1;    // [k=64][n=128 pad->136]

    const int t = threadIdx.x, w = t >> 5, lane = t & 31;
    const int g = lane >> 2, tq = lane & 3;
    const int m0w = (w & 1) * 64, n0w = (w >> 1) * 32;
    const int jt = blockIdx.x;                 // 0..3 Wq, 4..11 Wkv
    const int p0 = blockIdx.y * 128;
    const int b  = p0 >> 14;
    const int y  = (p0 & (HWH - 1)) >> 7;

    float acc[4][4][4];
    #pragma unroll
    for (int mt = 0; mt < 4; mt++)
        #pragma unroll
        for (int nt = 0; nt < 4; nt++)
            #pragma unroll
            for (int e = 0; e < 4; e++) acc[mt][nt][e] = 0.f;

    for (int kc = 0; kc < 2; kc++) {
        const int K0 = kc * 64;
        __syncthreads();
        const float* xb = x + ((size_t)(b * CC + K0) * 128 + y) * 128;
        for (int idx = t; idx < 64 * 32; idx += 256) {
            int k = idx >> 5, m4 = (idx & 31) * 4;
            float4 v = *(const float4*)(xb + (size_t)k * HWH + m4);
            float* d = &As[k * S1 + m4];
            d[0] = f2tff(v.x); d[1] = f2tff(v.y); d[2] = f2tff(v.z); d[3] = f2tff(v.w);
        }
        if (jt < 4) {
            const float* Wb = Wq + (size_t)K0 * INNER + jt * 128;
            for (int idx = t; idx < 64 * 32; idx += 256) {
                int k = idx >> 5, n4 = (idx & 31) * 4;
                float4 v = *(const float4*)(Wb + (size_t)k * INNER + n4);
                float* d = &Bs[k * S1 + n4];
                d[0] = f2tff(v.x * 0.125f); d[1] = f2tff(v.y * 0.125f);
                d[2] = f2tff(v.z * 0.125f); d[3] = f2tff(v.w * 0.125f);
            }
        } else {
            const float* Wb = Wkv + (size_t)K0 * 1024 + (jt - 4) * 128;
            for (int idx = t; idx < 64 * 32; idx += 256) {
                int k = idx >> 5, n4 = (idx & 31) * 4;
                float4 v = *(const float4*)(Wb + (size_t)k * 1024 + n4);
                float* d = &Bs[k * S1 + n4];
                d[0] = f2tff(v.x); d[1] = f2tff(v.y); d[2] = f2tff(v.z); d[3] = f2tff(v.w);
            }
        }
        __syncthreads();

        #pragma unroll
        for (int ks = 0; ks < 8; ks++) {
            const int k0 = ks * 8;
            uint32_t af[4][4];
            #pragma unroll
            for (int mt = 0; mt < 4; mt++) {
                int m = m0w + mt * 16 + g;
                af[mt][0] = __float_as_uint(As[(k0 + tq) * S1 + m]);
                af[mt][1] = __float_as_uint(As[(k0 + tq) * S1 + m + 8]);
                af[mt][2] = __float_as_uint(As[(k0 + tq + 4) * S1 + m]);
                af[mt][3] = __float_as_uint(As[(k0 + tq + 4) * S1 + m + 8]);
            }
            #pragma unroll
            for (int nt = 0; nt < 4; nt++) {
                int n = n0w + nt * 8 + g;
                uint32_t b0 = __float_as_uint(Bs[(k0 + tq) * S1 + n]);
                uint32_t b1 = __float_as_uint(Bs[(k0 + tq + 4) * S1 + n]);
                #pragma unroll
                for (int mt = 0; mt < 4; mt++)
                    mma8(acc[mt][nt], af[mt][0], af[mt][1], af[mt][2], af[mt][3], b0, b1);
            }
        }
    }

    const int colb = jt * 128;
    #pragma unroll
    for (int mt = 0; mt < 4; mt++) {
        int m = m0w + mt * 16 + g;
        #pragma unroll
        for (int nt = 0; nt < 4; nt++) {
            int n = colb + n0w + nt * 8 + tq * 2;
            *(float2*)&g_P[(size_t)(p0 + m) * NP + n]     = make_float2(acc[mt][nt][0], acc[mt][nt][1]);
            *(float2*)&g_P[(size_t)(p0 + m + 8) * NP + n] = make_float2(acc[mt][nt][2], acc[mt][nt][3]);
        }
    }
}

// ---------------------------------------------------------------------------
// Kernel 2: halo attention per (nb, head, b). 512 threads = 16 warps, TF32 MMA.
// S: M=64, N=224 (196 + zero pad), K=64. 16 warps = 4 m-tiles x 4 n-quarters(56).
// O: M=64, N=64, K=200. 16 warps = 4 m-tiles x 4 n-blocks(16).
// smem: qs[64][68] ks[224][68] vs[200][72] ss[64][204] mask[224]
// ---------------------------------------------------------------------------
#define SQ 68
#define SK 68
#define SV 72
#define SS 204
__global__ void __launch_bounds__(512) k_attn() {
    extern __shared__ float sm[];
    float* qs    = sm;                   // 64*68
    float* ks    = qs + 64 * SQ;         // 224*68 (rows 196..223 zero)
    float* vs    = ks + 224 * SK;        // 200*72 (rows 196..199 zero)
    float* ss    = vs + 200 * SV;        // 64*204 (cols 0..199; col 200 = 1/sum)
    float* maskv = ss + 64 * SS;         // [224]  1=valid, 0=masked

    const int t = threadIdx.x, w = t >> 5, lane = t & 31;
    const int g = lane >> 2, tq = lane & 3;
    const int nb   = blockIdx.x;
    const int head = blockIdx.y;
    const int b    = blockIdx.z;
    const int by = nb >> 4, bx = nb & 15;
    const int qoff = head * 64;
    const int pbase = b * HWH;

    // ---- mask LUT ----
    if (t < 224) {
        int j = t;
        bool valid = false;
        if (j < 196) {
            int wy = j / 14, wx = j % 14;
            int gy = by * 8 - 3 + wy, gx = bx * 8 - 3 + wx;
            valid = ((unsigned)gy < 128u) && ((unsigned)gx < 128u);
        }
        maskv[j] = valid ? 1.f : 0.f;
    }
    // ---- gather q (pre-scaled) ----
    for (int idx = t; idx < 64 * 16; idx += 512) {
        int i = idx >> 4, d4 = (idx & 15) * 4;
        int gy = by * 8 + (i >> 3), gx = bx * 8 + (i & 7);
        float4 v = *(const float4*)&g_P[(size_t)(pbase + gy * 128 + gx) * NP + qoff + d4];
        float* d = &qs[i * SQ + d4];
        d[0] = f2tff(v.x); d[1] = f2tff(v.y); d[2] = f2tff(v.z); d[3] = f2tff(v.w);
    }
    // ---- gather k, v halo windows ----
    for (int idx = t; idx < 196 * 16; idx += 512) {
        int j = idx >> 4, d4 = (idx & 15) * 4;
        int wy = j / 14, wx = j % 14;
        int gy = by * 8 - 3 + wy, gx = bx * 8 - 3 + wx;
        bool valid = ((unsigned)gy < 128u) && ((unsigned)gx < 128u);
        float4 kv0 = make_float4(0.f, 0.f, 0.f, 0.f), kv1 = kv0;
        if (valid) {
            size_t base = (size_t)(pbase + gy * 128 + gx) * NP + 512 + qoff + d4;
            kv0 = *(const float4*)&g_P[base];
            kv1 = *(const float4*)&g_P[base + 512];
        }
        float* dk = &ks[j * SK + d4];
        dk[0] = f2tff(kv0.x); dk[1] = f2tff(kv0.y); dk[2] = f2tff(kv0.z); dk[3] = f2tff(kv0.w);
        float* dv = &vs[j * SV + d4];
        dv[0] = f2tff(kv1.x); dv[1] = f2tff(kv1.y); dv[2] = f2tff(kv1.z); dv[3] = f2tff(kv1.w);
    }
    // zero pad rows: ks 196..223, vs 196..199
    for (int idx = t; idx < 28 * SK; idx += 512) ks[196 * SK + idx] = 0.f;
    for (int idx = t; idx < 4 * SV; idx += 512) vs[196 * SV + idx] = 0.f;
    __syncthreads();

    const int m0 = (w & 3) * 16;
    // ---- S = q @ k^T : warp -> m-tile (w&3), n-quarter (w>>2)*56, 7 n-tiles ----
    {
        const int n0q = (w >> 2) * 56;
        float sacc[7][4];
        #pragma unroll
        for (int nt = 0; nt < 7; nt++)
            #pragma unroll
            for (int e = 0; e < 4; e++) sacc[nt][e] = 0.f;

        #pragma unroll
        for (int ks8 = 0; ks8 < 8; ks8++) {
            const int k0 = ks8 * 8;
            uint32_t a0 = __float_as_uint(qs[(m0 + g) * SQ + k0 + tq]);
            uint32_t a1 = __float_as_uint(qs[(m0 + g + 8) * SQ + k0 + tq]);
            uint32_t a2 = __float_as_uint(qs[(m0 + g) * SQ + k0 + tq + 4]);
            uint32_t a3 = __float_as_uint(qs[(m0 + g + 8) * SQ + k0 + tq + 4]);
            #pragma unroll
            for (int nt = 0; nt < 7; nt++) {
                int n = n0q + nt * 8 + g;
                uint32_t b0 = __float_as_uint(ks[n * SK + k0 + tq]);
                uint32_t b1 = __float_as_uint(ks[n * SK + k0 + tq + 4]);
                mma8(sacc[nt], a0, a1, a2, a3, b0, b1);
            }
        }
        // store with mask LUT (no div/mod)
        const int rA = m0 + g, rB = rA + 8;
        #pragma unroll
        for (int nt = 0; nt < 7; nt++) {
            int jA = n0q + nt * 8 + tq * 2, jB = jA + 1;
            if (jA < 200) {
                bool vA = maskv[jA] != 0.f;
                ss[rA * SS + jA] = vA ? sacc[nt][0] : MAXNEG;
                ss[rB * SS + jA] = vA ? sacc[nt][2] : MAXNEG;
            }
            if (jB < 200) {
                bool vB = maskv[jB] != 0.f;
                ss[rA * SS + jB] = vB ? sacc[nt][1] : MAXNEG;
                ss[rB * SS + jB] = vB ? sacc[nt][3] : MAXNEG;
            }
        }
    }
    __syncthreads();

    // ---- softmax: 8 lanes per row over 200 cols ----
    {
        const int i = t >> 3, part = t & 7;
        float* row = &ss[i * SS];
        float m = MAXNEG;
        #pragma unroll
        for (int jj = part; jj < 200; jj += 8) m = fmaxf(m, row[jj]);
        m = fmaxf(m, __shfl_xor_sync(0xffffffffu, m, 1));
        m = fmaxf(m, __shfl_xor_sync(0xffffffffu, m, 2));
        m = fmaxf(m, __shfl_xor_sync(0xffffffffu, m, 4));
        float sum = 0.f;
        #pragma unroll
        for (int jj = part; jj < 200; jj += 8) {
            float e = __expf(row[jj] - m);
            sum += e;
            row[jj] = f2tff(e);
        }
        sum += __shfl_xor_sync(0xffffffffu, sum, 1);
        sum += __shfl_xor_sync(0xffffffffu, sum, 2);
        sum += __shfl_xor_sync(0xffffffffu, sum, 4);
        if (part == 0) row[200] = 1.0f / sum;
    }
    __syncthreads();

    // ---- O = attn @ v : warp -> m-tile (w&3), n-block (w>>2)*16, 2 n-tiles ----
    {
        const int n0w = (w >> 2) * 16;
        float oacc[2][4];
        #pragma unroll
        for (int nt = 0; nt < 2; nt++)
            #pragma unroll
            for (int e = 0; e < 4; e++) oacc[nt][e] = 0.f;

        #pragma unroll 5
        for (int ks8 = 0; ks8 < 25; ks8++) {
            const int k0 = ks8 * 8;
            uint32_t a0 = __float_as_uint(ss[(m0 + g) * SS + k0 + tq]);
            uint32_t a1 = __float_as_uint(ss[(m0 + g + 8) * SS + k0 + tq]);
            uint32_t a2 = __float_as_uint(ss[(m0 + g) * SS + k0 + tq + 4]);
            uint32_t a3 = __float_as_uint(ss[(m0 + g + 8) * SS + k0 + tq + 4]);
            #pragma unroll
            for (int nt = 0; nt < 2; nt++) {
                int n = n0w + nt * 8 + g;
                uint32_t b0 = __float_as_uint(vs[(k0 + tq) * SV + n]);
                uint32_t b1 = __float_as_uint(vs[(k0 + tq + 4) * SV + n]);
                mma8(oacc[nt], a0, a1, a2, a3, b0, b1);
            }
        }
        // epilogue: normalize + scatter to g_AO
        const int rA = m0 + g, rB = rA + 8;
        const float invA = ss[rA * SS + 200];
        const float invB = ss[rB * SS + 200];
        const int gyA = by * 8 + (rA >> 3), gxA = bx * 8 + (rA & 7);
        const int gyB = by * 8 + (rB >> 3), gxB = bx * 8 + (rB & 7);
        float* dstA = &g_AO[(size_t)(pbase + gyA * 128 + gxA) * INNER + qoff];
        float* dstB = &g_AO[(size_t)(pbase + gyB * 128 + gxB) * INNER + qoff];
        #pragma unroll
        for (int nt = 0; nt < 2; nt++) {
            int n = n0w + nt * 8 + tq * 2;
            *(float2*)&dstA[n] = make_float2(oacc[nt][0] * invA, oacc[nt][1] * invA);
            *(float2*)&dstB[n] = make_float2(oacc[nt][2] * invB, oacc[nt][3] * invB);
        }
    }
}

// ---------------------------------------------------------------------------
// Kernel 3: out = AO @ Wo + bo, transposed store. TF32 MMA.
// grid 512, block 256 = 8 warps (2m x 4n). K=512 in 8 chunks of 64.
// ---------------------------------------------------------------------------
#define SA3 68
#define SB3 136
__global__ void __launch_bounds__(256) k_out(const float* __restrict__ Wo,
                                             const float* __restrict__ bo,
                                             float* __restrict__ out) {
    extern __shared__ float sm[];
    float* As = sm;              // [m=128][k=64 pad->68]
    float* Bs = sm + 128 * SA3;  // [k=64][n=128 pad->136]

    const int t = threadIdx.x, w = t >> 5, lane = t & 31;
    const int g = lane >> 2, tq = lane & 3;
    const int m0w = (w & 1) * 64, n0w = (w >> 1) * 32;
    const int p0 = blockIdx.x * 128;
    const int b  = p0 >> 14;
    const int y  = (p0 & (HWH - 1)) >> 7;

    float acc[4][4][4];
    #pragma unroll
    for (int mt = 0; mt < 4; mt++)
        #pragma unroll
        for (int nt = 0; nt < 4; nt++)
            #pragma unroll
            for (int e = 0; e < 4; e++) acc[mt][nt][e] = 0.f;

    for (int kc = 0; kc < 8; kc++) {
        const int K0 = kc * 64;
        __syncthreads();
        for (int idx = t; idx < 128 * 16; idx += 256) {
            int m = idx >> 4, k4 = (idx & 15) * 4;
            float4 v = *(const float4*)&g_AO[(size_t)(p0 + m) * INNER + K0 + k4];
            float* d = &As[m * SA3 + k4];
            d[0] = f2tff(v.x); d[1] = f2tff(v.y); d[2] = f2tff(v.z); d[3] = f2tff(v.w);
        }
        for (int idx = t; idx < 64 * 32; idx += 256) {
            int k = idx >> 5, n4 = (idx & 31) * 4;
            float4 v = *(const float4*)&Wo[(size_t)(K0 + k) * CC + n4];
            float* d = &Bs[k * SB3 + n4];
            d[0] = f2tff(v.x); d[1] = f2tff(v.y); d[2] = f2tff(v.z); d[3] = f2tff(v.w);
        }
        __syncthreads();

        #pragma unroll
        for (int ks8 = 0; ks8 < 8; ks8++) {
            const int k0 = ks8 * 8;
            uint32_t af[4][4];
            #pragma unroll
            for (int mt = 0; mt < 4; mt++) {
                int m = m0w + mt * 16 + g;
                af[mt][0] = __float_as_uint(As[m * SA3 + k0 + tq]);
                af[mt][1] = __float_as_uint(As[(m + 8) * SA3 + k0 + tq]);
                af[mt][2] = __float_as_uint(As[m * SA3 + k0 + tq + 4]);
                af[mt][3] = __float_as_uint(As[(m + 8) * SA3 + k0 + tq + 4]);
            }
            #pragma unroll
            for (int nt = 0; nt < 4; nt++) {
                int n = n0w + nt * 8 + g;
                uint32_t b0 = __float_as_uint(Bs[(k0 + tq) * SB3 + n]);
                uint32_t b1 = __float_as_uint(Bs[(k0 + tq + 4) * SB3 + n]);
                #pragma unroll
                for (int mt = 0; mt < 4; mt++)
                    mma8(acc[mt][nt], af[mt][0], af[mt][1], af[mt][2], af[mt][3], b0, b1);
            }
        }
    }

    // epilogue: out[b][n][y][m] = acc + bo[n]
    #pragma unroll
    for (int nt = 0; nt < 4; nt++) {
        int nA = n0w + nt * 8 + tq * 2, nB = nA + 1;
        float biasA = bo[nA], biasB = bo[nB];
        float* colA = out + (size_t)(b * CC + nA) * HWH + y * 128;
        float* colB = out + (size_t)(b * CC + nB) * HWH + y * 128;
        #pragma unroll
        for (int mt = 0; mt < 4; mt++) {
            int m = m0w + mt * 16 + g;
            colA[m]     = acc[mt][nt][0] + biasA;
            colB[m]     = acc[mt][nt][1] + biasB;
            colA[m + 8] = acc[mt][nt][2] + biasA;
            colB[m + 8] = acc[mt][nt][3] + biasB;
        }
    }
}

extern "C" void kernel_launch(void* const* d_in, const int* in_sizes, int n_in,
                              void* d_out, int out_size) {
    const float* x   = (const float*)d_in[0];
    const float* Wq  = (const float*)d_in[1];
    const float* Wkv = (const float*)d_in[2];
    const float* Wo  = (const float*)d_in[3];
    const float* bo  = (const float*)d_in[4];
    float* out = (float*)d_out;

    const int smem1 = 2 * 64 * S1 * 4;                                        // 69632
    const int smem2 = (64 * SQ + 224 * SK + 200 * SV + 64 * SS + 224) * 4;    // 189056
    const int smem3 = (128 * SA3 + 64 * SB3) * 4;                             // 69632

    cudaFuncSetAttribute(k_proj, cudaFuncAttributeMaxDynamicSharedMemorySize, smem1);
    cudaFuncSetAttribute(k_attn, cudaFuncAttributeMaxDynamicSharedMemorySize, smem2);
    cudaFuncSetAttribute(k_out,  cudaFuncAttributeMaxDynamicSharedMemorySize, smem3);

    dim3 g1(12, 512);
    k_proj<<<g1, 256, smem1>>>(x, Wq, Wkv);

    dim3 g2(256, 8, 4);
    k_attn<<<g2, 512, smem2>>>();

    dim3 g3(512);
    k_out<<<g3, 256, smem3>>>(Wo, bo, out);
}

// round 6
// speedup vs baseline: 2.7381x; 1.0292x over previous
#include <cuda_runtime.h>
#include <stdint.h>
#include <math.h>

#define BB 4
#define CC 128
#define HWH 16384
#define NPIX 65536
#define INNER 512
#define NP 1536
#define MAXNEG -3.402823466e38f

__device__ float g_P[(size_t)NPIX * NP];      // per-pixel [q(512, pre-scaled) | k(512) | v(512)]
__device__ float g_AO[(size_t)NPIX * INNER];

__device__ __forceinline__ uint32_t f2tf(float f) {
    uint32_t u; asm("cvt.rna.tf32.f32 %0, %1;" : "=r"(u) : "f"(f)); return u;
}
__device__ __forceinline__ float f2tff(float f) { return __uint_as_float(f2tf(f)); }

__device__ __forceinline__ void mma8(float* c,
                                     uint32_t a0, uint32_t a1, uint32_t a2, uint32_t a3,
                                     uint32_t b0, uint32_t b1) {
    asm volatile("mma.sync.aligned.m16n8k8.row.col.f32.tf32.tf32.f32 "
        "{%0,%1,%2,%3}, {%4,%5,%6,%7}, {%8,%9}, {%0,%1,%2,%3};"
        : "+f"(c[0]), "+f"(c[1]), "+f"(c[2]), "+f"(c[3])
        : "r"(a0), "r"(a1), "r"(a2), "r"(a3), "r"(b0), "r"(b1));
}

// ---------------------------------------------------------------------------
// Kernel 1: P[p,:] = x_pixel[p,:] @ [Wq*0.125 | Wkv].  TF32 MMA.
// ---------------------------------------------------------------------------
#define S1 136
__global__ void __launch_bounds__(256) k_proj(const float* __restrict__ x,
                                              const float* __restrict__ Wq,
                                              const float* __restrict__ Wkv) {
    extern __shared__ float sm[];
    float* As = sm;              // [k=64][m=128 pad->136]
    float* Bs = sm + 64 * S1;    // [k=64][n=128 pad->136]

    const int t = threadIdx.x, w = t >> 5, lane = t & 31;
    const int g = lane >> 2, tq = lane & 3;
    const int m0w = (w & 1) * 64, n0w = (w >> 1) * 32;
    const int jt = blockIdx.x;                 // 0..3 Wq, 4..11 Wkv
    const int p0 = blockIdx.y * 128;
    const int b  = p0 >> 14;
    const int y  = (p0 & (HWH - 1)) >> 7;

    float acc[4][4][4];
    #pragma unroll
    for (int mt = 0; mt < 4; mt++)
        #pragma unroll
        for (int nt = 0; nt < 4; nt++)
            #pragma unroll
            for (int e = 0; e < 4; e++) acc[mt][nt][e] = 0.f;

    for (int kc = 0; kc < 2; kc++) {
        const int K0 = kc * 64;
        __syncthreads();
        const float* xb = x + ((size_t)(b * CC + K0) * 128 + y) * 128;
        for (int idx = t; idx < 64 * 32; idx += 256) {
            int k = idx >> 5, m4 = (idx & 31) * 4;
            float4 v = *(const float4*)(xb + (size_t)k * HWH + m4);
            float* d = &As[k * S1 + m4];
            d[0] = f2tff(v.x); d[1] = f2tff(v.y); d[2] = f2tff(v.z); d[3] = f2tff(v.w);
        }
        if (jt < 4) {
            const float* Wb = Wq + (size_t)K0 * INNER + jt * 128;
            for (int idx = t; idx < 64 * 32; idx += 256) {
                int k = idx >> 5, n4 = (idx & 31) * 4;
                float4 v = *(const float4*)(Wb + (size_t)k * INNER + n4);
                float* d = &Bs[k * S1 + n4];
                d[0] = f2tff(v.x * 0.125f); d[1] = f2tff(v.y * 0.125f);
                d[2] = f2tff(v.z * 0.125f); d[3] = f2tff(v.w * 0.125f);
            }
        } else {
            const float* Wb = Wkv + (size_t)K0 * 1024 + (jt - 4) * 128;
            for (int idx = t; idx < 64 * 32; idx += 256) {
                int k = idx >> 5, n4 = (idx & 31) * 4;
                float4 v = *(const float4*)(Wb + (size_t)k * 1024 + n4);
                float* d = &Bs[k * S1 + n4];
                d[0] = f2tff(v.x); d[1] = f2tff(v.y); d[2] = f2tff(v.z); d[3] = f2tff(v.w);
            }
        }
        __syncthreads();

        #pragma unroll
        for (int ks = 0; ks < 8; ks++) {
            const int k0 = ks * 8;
            uint32_t af[4][4];
            #pragma unroll
            for (int mt = 0; mt < 4; mt++) {
                int m = m0w + mt * 16 + g;
                af[mt][0] = __float_as_uint(As[(k0 + tq) * S1 + m]);
                af[mt][1] = __float_as_uint(As[(k0 + tq) * S1 + m + 8]);
                af[mt][2] = __float_as_uint(As[(k0 + tq + 4) * S1 + m]);
                af[mt][3] = __float_as_uint(As[(k0 + tq + 4) * S1 + m + 8]);
            }
            #pragma unroll
            for (int nt = 0; nt < 4; nt++) {
                int n = n0w + nt * 8 + g;
                uint32_t b0 = __float_as_uint(Bs[(k0 + tq) * S1 + n]);
                uint32_t b1 = __float_as_uint(Bs[(k0 + tq + 4) * S1 + n]);
                #pragma unroll
                for (int mt = 0; mt < 4; mt++)
                    mma8(acc[mt][nt], af[mt][0], af[mt][1], af[mt][2], af[mt][3], b0, b1);
            }
        }
    }

    const int colb = jt * 128;
    #pragma unroll
    for (int mt = 0; mt < 4; mt++) {
        int m = m0w + mt * 16 + g;
        #pragma unroll
        for (int nt = 0; nt < 4; nt++) {
            int n = colb + n0w + nt * 8 + tq * 2;
            *(float2*)&g_P[(size_t)(p0 + m) * NP + n]     = make_float2(acc[mt][nt][0], acc[mt][nt][1]);
            *(float2*)&g_P[(size_t)(p0 + m + 8) * NP + n] = make_float2(acc[mt][nt][2], acc[mt][nt][3]);
        }
    }
}

// ---------------------------------------------------------------------------
// Kernel 2: halo attention per (nb, head, b). 1024 threads = 32 warps, TF32 MMA.
// S-phase: 4 m-tiles x 8 n-groups (groups 0-3: 4 tiles over cols 0..127,
//          groups 4-7: 3 tiles over cols 128..223).
// O-phase: 4 m-tiles x 8 n-tiles(8), K=200 (25 k-steps).
// smem: qs[64][68] ks[224][68] vs[200][72] ss[64][204] mask[224]
// ---------------------------------------------------------------------------
#define SQ 68
#define SK 68
#define SV 72
#define SS 204
__global__ void __launch_bounds__(1024) k_attn() {
    extern __shared__ float sm[];
    float* qs    = sm;                   // 64*68
    float* ks    = qs + 64 * SQ;         // 224*68 (rows 196..223 zero)
    float* vs    = ks + 224 * SK;        // 200*72 (rows 196..199 zero)
    float* ss    = vs + 200 * SV;        // 64*204 (cols 0..199; col 200 = 1/sum)
    float* maskv = ss + 64 * SS;         // [224]  1=valid, 0=masked

    const int t = threadIdx.x, w = t >> 5, lane = t & 31;
    const int g = lane >> 2, tq = lane & 3;
    const int nb   = blockIdx.x;
    const int head = blockIdx.y;
    const int b    = blockIdx.z;
    const int by = nb >> 4, bx = nb & 15;
    const int qoff = head * 64;
    const int pbase = b * HWH;

    // ---- mask LUT ----
    if (t < 224) {
        int j = t;
        bool valid = false;
        if (j < 196) {
            int wy = j / 14, wx = j % 14;
            int gy = by * 8 - 3 + wy, gx = bx * 8 - 3 + wx;
            valid = ((unsigned)gy < 128u) && ((unsigned)gx < 128u);
        }
        maskv[j] = valid ? 1.f : 0.f;
    }
    // ---- gather q (pre-scaled) ----
    for (int idx = t; idx < 64 * 16; idx += 1024) {
        int i = idx >> 4, d4 = (idx & 15) * 4;
        int gy = by * 8 + (i >> 3), gx = bx * 8 + (i & 7);
        float4 v = *(const float4*)&g_P[(size_t)(pbase + gy * 128 + gx) * NP + qoff + d4];
        float* d = &qs[i * SQ + d4];
        d[0] = f2tff(v.x); d[1] = f2tff(v.y); d[2] = f2tff(v.z); d[3] = f2tff(v.w);
    }
    // ---- gather k, v halo windows ----
    for (int idx = t; idx < 196 * 16; idx += 1024) {
        int j = idx >> 4, d4 = (idx & 15) * 4;
        int wy = j / 14, wx = j % 14;
        int gy = by * 8 - 3 + wy, gx = bx * 8 - 3 + wx;
        bool valid = ((unsigned)gy < 128u) && ((unsigned)gx < 128u);
        float4 kv0 = make_float4(0.f, 0.f, 0.f, 0.f), kv1 = kv0;
        if (valid) {
            size_t base = (size_t)(pbase + gy * 128 + gx) * NP + 512 + qoff + d4;
            kv0 = *(const float4*)&g_P[base];
            kv1 = *(const float4*)&g_P[base + 512];
        }
        float* dk = &ks[j * SK + d4];
        dk[0] = f2tff(kv0.x); dk[1] = f2tff(kv0.y); dk[2] = f2tff(kv0.z); dk[3] = f2tff(kv0.w);
        float* dv = &vs[j * SV + d4];
        dv[0] = f2tff(kv1.x); dv[1] = f2tff(kv1.y); dv[2] = f2tff(kv1.z); dv[3] = f2tff(kv1.w);
    }
    // zero pad rows: ks 196..223, vs 196..199
    for (int idx = t; idx < 28 * SK; idx += 1024) ks[196 * SK + idx] = 0.f;
    if (t < 4 * SV) vs[196 * SV + t] = 0.f;
    __syncthreads();

    const int m0 = (w & 3) * 16;
    const int nq = w >> 2;                        // 0..7
    // ---- S = q @ k^T ----
    {
        const int ntiles = nq < 4 ? 4 : 3;
        const int n0q = nq < 4 ? nq * 32 : 128 + (nq - 4) * 24;
        float sacc[4][4];
        #pragma unroll
        for (int nt = 0; nt < 4; nt++)
            #pragma unroll
            for (int e = 0; e < 4; e++) sacc[nt][e] = 0.f;

        #pragma unroll
        for (int ks8 = 0; ks8 < 8; ks8++) {
            const int k0 = ks8 * 8;
            uint32_t a0 = __float_as_uint(qs[(m0 + g) * SQ + k0 + tq]);
            uint32_t a1 = __float_as_uint(qs[(m0 + g + 8) * SQ + k0 + tq]);
            uint32_t a2 = __float_as_uint(qs[(m0 + g) * SQ + k0 + tq + 4]);
            uint32_t a3 = __float_as_uint(qs[(m0 + g + 8) * SQ + k0 + tq + 4]);
            #pragma unroll
            for (int nt = 0; nt < 4; nt++) {
                if (nt < ntiles) {
                    int n = n0q + nt * 8 + g;
                    uint32_t b0 = __float_as_uint(ks[n * SK + k0 + tq]);
                    uint32_t b1 = __float_as_uint(ks[n * SK + k0 + tq + 4]);
                    mma8(sacc[nt], a0, a1, a2, a3, b0, b1);
                }
            }
        }
        // store with mask LUT
        const int rA = m0 + g, rB = rA + 8;
        #pragma unroll
        for (int nt = 0; nt < 4; nt++) {
            if (nt < ntiles) {
                int jA = n0q + nt * 8 + tq * 2, jB = jA + 1;
                if (jA < 200) {
                    bool vA = maskv[jA] != 0.f;
                    ss[rA * SS + jA] = vA ? sacc[nt][0] : MAXNEG;
                    ss[rB * SS + jA] = vA ? sacc[nt][2] : MAXNEG;
                }
                if (jB < 200) {
                    bool vB = maskv[jB] != 0.f;
                    ss[rA * SS + jB] = vB ? sacc[nt][1] : MAXNEG;
                    ss[rB * SS + jB] = vB ? sacc[nt][3] : MAXNEG;
                }
            }
        }
    }
    __syncthreads();

    // ---- softmax: 16 lanes per row over 200 cols ----
    {
        const int i = t >> 4, part = t & 15;
        float* row = &ss[i * SS];
        float m = MAXNEG;
        #pragma unroll
        for (int jj = part; jj < 200; jj += 16) m = fmaxf(m, row[jj]);
        m = fmaxf(m, __shfl_xor_sync(0xffffffffu, m, 1));
        m = fmaxf(m, __shfl_xor_sync(0xffffffffu, m, 2));
        m = fmaxf(m, __shfl_xor_sync(0xffffffffu, m, 4));
        m = fmaxf(m, __shfl_xor_sync(0xffffffffu, m, 8));
        float sum = 0.f;
        #pragma unroll
        for (int jj = part; jj < 200; jj += 16) {
            float e = __expf(row[jj] - m);
            sum += e;
            row[jj] = f2tff(e);
        }
        sum += __shfl_xor_sync(0xffffffffu, sum, 1);
        sum += __shfl_xor_sync(0xffffffffu, sum, 2);
        sum += __shfl_xor_sync(0xffffffffu, sum, 4);
        sum += __shfl_xor_sync(0xffffffffu, sum, 8);
        if (part == 0) row[200] = 1.0f / sum;
    }
    __syncthreads();

    // ---- O = attn @ v : warp -> m-tile (w&3), n-tile (w>>2)*8 ----
    {
        const int n0w = nq * 8;
        float oacc[4];
        #pragma unroll
        for (int e = 0; e < 4; e++) oacc[e] = 0.f;

        #pragma unroll 5
        for (int ks8 = 0; ks8 < 25; ks8++) {
            const int k0 = ks8 * 8;
            uint32_t a0 = __float_as_uint(ss[(m0 + g) * SS + k0 + tq]);
            uint32_t a1 = __float_as_uint(ss[(m0 + g + 8) * SS + k0 + tq]);
            uint32_t a2 = __float_as_uint(ss[(m0 + g) * SS + k0 + tq + 4]);
            uint32_t a3 = __float_as_uint(ss[(m0 + g + 8) * SS + k0 + tq + 4]);
            int n = n0w + g;
            uint32_t b0 = __float_as_uint(vs[(k0 + tq) * SV + n]);
            uint32_t b1 = __float_as_uint(vs[(k0 + tq + 4) * SV + n]);
            mma8(oacc, a0, a1, a2, a3, b0, b1);
        }
        // epilogue: normalize + scatter to g_AO
        const int rA = m0 + g, rB = rA + 8;
        const float invA = ss[rA * SS + 200];
        const float invB = ss[rB * SS + 200];
        const int gyA = by * 8 + (rA >> 3), gxA = bx * 8 + (rA & 7);
        const int gyB = by * 8 + (rB >> 3), gxB = bx * 8 + (rB & 7);
        float* dstA = &g_AO[(size_t)(pbase + gyA * 128 + gxA) * INNER + qoff];
        float* dstB = &g_AO[(size_t)(pbase + gyB * 128 + gxB) * INNER + qoff];
        int n = n0w + tq * 2;
        *(float2*)&dstA[n] = make_float2(oacc[0] * invA, oacc[1] * invA);
        *(float2*)&dstB[n] = make_float2(oacc[2] * invB, oacc[3] * invB);
    }
}

// ---------------------------------------------------------------------------
// Kernel 3: out = AO @ Wo + bo, transposed store. TF32 MMA.
// ---------------------------------------------------------------------------
#define SA3 68
#define SB3 136
__global__ void __launch_bounds__(256) k_out(const float* __restrict__ Wo,
                                             const float* __restrict__ bo,
                                             float* __restrict__ out) {
    extern __shared__ float sm[];
    float* As = sm;              // [m=128][k=64 pad->68]
    float* Bs = sm + 128 * SA3;  // [k=64][n=128 pad->136]

    const int t = threadIdx.x, w = t >> 5, lane = t & 31;
    const int g = lane >> 2, tq = lane & 3;
    const int m0w = (w & 1) * 64, n0w = (w >> 1) * 32;
    const int p0 = blockIdx.x * 128;
    const int b  = p0 >> 14;
    const int y  = (p0 & (HWH - 1)) >> 7;

    float acc[4][4][4];
    #pragma unroll
    for (int mt = 0; mt < 4; mt++)
        #pragma unroll
        for (int nt = 0; nt < 4; nt++)
            #pragma unroll
            for (int e = 0; e < 4; e++) acc[mt][nt][e] = 0.f;

    for (int kc = 0; kc < 8; kc++) {
        const int K0 = kc * 64;
        __syncthreads();
        for (int idx = t; idx < 128 * 16; idx += 256) {
            int m = idx >> 4, k4 = (idx & 15) * 4;
            float4 v = *(const float4*)&g_AO[(size_t)(p0 + m) * INNER + K0 + k4];
            float* d = &As[m * SA3 + k4];
            d[0] = f2tff(v.x); d[1] = f2tff(v.y); d[2] = f2tff(v.z); d[3] = f2tff(v.w);
        }
        for (int idx = t; idx < 64 * 32; idx += 256) {
            int k = idx >> 5, n4 = (idx & 31) * 4;
            float4 v = *(const float4*)&Wo[(size_t)(K0 + k) * CC + n4];
            float* d = &Bs[k * SB3 + n4];
            d[0] = f2tff(v.x); d[1] = f2tff(v.y); d[2] = f2tff(v.z); d[3] = f2tff(v.w);
        }
        __syncthreads();

        #pragma unroll
        for (int ks8 = 0; ks8 < 8; ks8++) {
            const int k0 = ks8 * 8;
            uint32_t af[4][4];
            #pragma unroll
            for (int mt = 0; mt < 4; mt++) {
                int m = m0w + mt * 16 + g;
                af[mt][0] = __float_as_uint(As[m * SA3 + k0 + tq]);
                af[mt][1] = __float_as_uint(As[(m + 8) * SA3 + k0 + tq]);
                af[mt][2] = __float_as_uint(As[m * SA3 + k0 + tq + 4]);
                af[mt][3] = __float_as_uint(As[(m + 8) * SA3 + k0 + tq + 4]);
            }
            #pragma unroll
            for (int nt = 0; nt < 4; nt++) {
                int n = n0w + nt * 8 + g;
                uint32_t b0 = __float_as_uint(Bs[(k0 + tq) * SB3 + n]);
                uint32_t b1 = __float_as_uint(Bs[(k0 + tq + 4) * SB3 + n]);
                #pragma unroll
                for (int mt = 0; mt < 4; mt++)
                    mma8(acc[mt][nt], af[mt][0], af[mt][1], af[mt][2], af[mt][3], b0, b1);
            }
        }
    }

    // epilogue: out[b][n][y][m] = acc + bo[n]
    #pragma unroll
    for (int nt = 0; nt < 4; nt++) {
        int nA = n0w + nt * 8 + tq * 2, nB = nA + 1;
        float biasA = bo[nA], biasB = bo[nB];
        float* colA = out + (size_t)(b * CC + nA) * HWH + y * 128;
        float* colB = out + (size_t)(b * CC + nB) * HWH + y * 128;
        #pragma unroll
        for (int mt = 0; mt < 4; mt++) {
            int m = m0w + mt * 16 + g;
            colA[m]     = acc[mt][nt][0] + biasA;
            colB[m]     = acc[mt][nt][1] + biasB;
            colA[m + 8] = acc[mt][nt][2] + biasA;
            colB[m + 8] = acc[mt][nt][3] + biasB;
        }
    }
}

extern "C" void kernel_launch(void* const* d_in, const int* in_sizes, int n_in,
                              void* d_out, int out_size) {
    const float* x   = (const float*)d_in[0];
    const float* Wq  = (const float*)d_in[1];
    const float* Wkv = (const float*)d_in[2];
    const float* Wo  = (const float*)d_in[3];
    const float* bo  = (const float*)d_in[4];
    float* out = (float*)d_out;

    const int smem1 = 2 * 64 * S1 * 4;                                        // 69632
    const int smem2 = (64 * SQ + 224 * SK + 200 * SV + 64 * SS + 224) * 4;    // 189056
    const int smem3 = (128 * SA3 + 64 * SB3) * 4;                             // 69632

    cudaFuncSetAttribute(k_proj, cudaFuncAttributeMaxDynamicSharedMemorySize, smem1);
    cudaFuncSetAttribute(k_attn, cudaFuncAttributeMaxDynamicSharedMemorySize, smem2);
    cudaFuncSetAttribute(k_out,  cudaFuncAttributeMaxDynamicSharedMemorySize, smem3);

    dim3 g1(12, 512);
    k_proj<<<g1, 256, smem1>>>(x, Wq, Wkv);

    dim3 g2(256, 8, 4);
    k_attn<<<g2, 1024, smem2>>>();

    dim3 g3(512);
    k_out<<<g3, 256, smem3>>>(Wo, bo, out);
}

// round 7
// speedup vs baseline: 3.1679x; 1.1570x over previous
#include <cuda_runtime.h>
#include <cuda_fp16.h>
#include <stdint.h>
#include <math.h>

#define BB 4
#define CC 128
#define HWH 16384
#define NPIX 65536
#define INNER 512
#define NP 1536
#define MAXNEG -3.402823466e38f

__device__ float g_P[(size_t)NPIX * NP];      // per-pixel [q(512, pre-scaled) | k(512) | v(512)]
__device__ float g_AO[(size_t)NPIX * INNER];

__device__ __forceinline__ uint32_t f2tf(float f) {
    uint32_t u; asm("cvt.rna.tf32.f32 %0, %1;" : "=r"(u) : "f"(f)); return u;
}
__device__ __forceinline__ float f2tff(float f) { return __uint_as_float(f2tf(f)); }

__device__ __forceinline__ void mma8(float* c,
                                     uint32_t a0, uint32_t a1, uint32_t a2, uint32_t a3,
                                     uint32_t b0, uint32_t b1) {
    asm volatile("mma.sync.aligned.m16n8k8.row.col.f32.tf32.tf32.f32 "
        "{%0,%1,%2,%3}, {%4,%5,%6,%7}, {%8,%9}, {%0,%1,%2,%3};"
        : "+f"(c[0]), "+f"(c[1]), "+f"(c[2]), "+f"(c[3])
        : "r"(a0), "r"(a1), "r"(a2), "r"(a3), "r"(b0), "r"(b1));
}
__device__ __forceinline__ void mma16h(float* c,
                                       uint32_t a0, uint32_t a1, uint32_t a2, uint32_t a3,
                                       uint32_t b0, uint32_t b1) {
    asm volatile("mma.sync.aligned.m16n8k16.row.col.f32.f16.f16.f32 "
        "{%0,%1,%2,%3}, {%4,%5,%6,%7}, {%8,%9}, {%0,%1,%2,%3};"
        : "+f"(c[0]), "+f"(c[1]), "+f"(c[2]), "+f"(c[3])
        : "r"(a0), "r"(a1), "r"(a2), "r"(a3), "r"(b0), "r"(b1));
}

// ---------------------------------------------------------------------------
// Kernel 1: P[p,:] = x_pixel[p,:] @ [Wq*0.125 | Wkv].  TF32 MMA. (unchanged)
// ---------------------------------------------------------------------------
#define S1 136
__global__ void __launch_bounds__(256) k_proj(const float* __restrict__ x,
                                              const float* __restrict__ Wq,
                                              const float* __restrict__ Wkv) {
    extern __shared__ float sm[];
    float* As = sm;
    float* Bs = sm + 64 * S1;

    const int t = threadIdx.x, w = t >> 5, lane = t & 31;
    const int g = lane >> 2, tq = lane & 3;
    const int m0w = (w & 1) * 64, n0w = (w >> 1) * 32;
    const int jt = blockIdx.x;
    const int p0 = blockIdx.y * 128;
    const int b  = p0 >> 14;
    const int y  = (p0 & (HWH - 1)) >> 7;

    float acc[4][4][4];
    #pragma unroll
    for (int mt = 0; mt < 4; mt++)
        #pragma unroll
        for (int nt = 0; nt < 4; nt++)
            #pragma unroll
            for (int e = 0; e < 4; e++) acc[mt][nt][e] = 0.f;

    for (int kc = 0; kc < 2; kc++) {
        const int K0 = kc * 64;
        __syncthreads();
        const float* xb = x + ((size_t)(b * CC + K0) * 128 + y) * 128;
        for (int idx = t; idx < 64 * 32; idx += 256) {
            int k = idx >> 5, m4 = (idx & 31) * 4;
            float4 v = *(const float4*)(xb + (size_t)k * HWH + m4);
            float* d = &As[k * S1 + m4];
            d[0] = f2tff(v.x); d[1] = f2tff(v.y); d[2] = f2tff(v.z); d[3] = f2tff(v.w);
        }
        if (jt < 4) {
            const float* Wb = Wq + (size_t)K0 * INNER + jt * 128;
            for (int idx = t; idx < 64 * 32; idx += 256) {
                int k = idx >> 5, n4 = (idx & 31) * 4;
                float4 v = *(const float4*)(Wb + (size_t)k * INNER + n4);
                float* d = &Bs[k * S1 + n4];
                d[0] = f2tff(v.x * 0.125f); d[1] = f2tff(v.y * 0.125f);
                d[2] = f2tff(v.z * 0.125f); d[3] = f2tff(v.w * 0.125f);
            }
        } else {
            const float* Wb = Wkv + (size_t)K0 * 1024 + (jt - 4) * 128;
            for (int idx = t; idx < 64 * 32; idx += 256) {
                int k = idx >> 5, n4 = (idx & 31) * 4;
                float4 v = *(const float4*)(Wb + (size_t)k * 1024 + n4);
                float* d = &Bs[k * S1 + n4];
                d[0] = f2tff(v.x); d[1] = f2tff(v.y); d[2] = f2tff(v.z); d[3] = f2tff(v.w);
            }
        }
        __syncthreads();

        #pragma unroll
        for (int ks = 0; ks < 8; ks++) {
            const int k0 = ks * 8;
            uint32_t af[4][4];
            #pragma unroll
            for (int mt = 0; mt < 4; mt++) {
                int m = m0w + mt * 16 + g;
                af[mt][0] = __float_as_uint(As[(k0 + tq) * S1 + m]);
                af[mt][1] = __float_as_uint(As[(k0 + tq) * S1 + m + 8]);
                af[mt][2] = __float_as_uint(As[(k0 + tq + 4) * S1 + m]);
                af[mt][3] = __float_as_uint(As[(k0 + tq + 4) * S1 + m + 8]);
            }
            #pragma unroll
            for (int nt = 0; nt < 4; nt++) {
                int n = n0w + nt * 8 + g;
                uint32_t b0 = __float_as_uint(Bs[(k0 + tq) * S1 + n]);
                uint32_t b1 = __float_as_uint(Bs[(k0 + tq + 4) * S1 + n]);
                #pragma unroll
                for (int mt = 0; mt < 4; mt++)
                    mma8(acc[mt][nt], af[mt][0], af[mt][1], af[mt][2], af[mt][3], b0, b1);
            }
        }
    }

    const int colb = jt * 128;
    #pragma unroll
    for (int mt = 0; mt < 4; mt++) {
        int m = m0w + mt * 16 + g;
        #pragma unroll
        for (int nt = 0; nt < 4; nt++) {
            int n = colb + n0w + nt * 8 + tq * 2;
            *(float2*)&g_P[(size_t)(p0 + m) * NP + n]     = make_float2(acc[mt][nt][0], acc[mt][nt][1]);
            *(float2*)&g_P[(size_t)(p0 + m + 8) * NP + n] = make_float2(acc[mt][nt][2], acc[mt][nt][3]);
        }
    }
}

// ---------------------------------------------------------------------------
// Kernel 2: halo attention. 1024 threads = 32 warps.
// S = QK^T in tf32 (4m x 8n warp split), register softmax (quad shuffles +
// 8x64 partial-stat arrays), P & V packed fp16 -> O = P·V with m16n8k16 f16
// MMA on 16 warps (4m x 4n).
// ---------------------------------------------------------------------------
#define SQ 68
#define SK 68
#define SVP 72     // vsP stride (uint32: half2 {v[2j2][d], v[2j2+1][d]})
#define SPP 116    // psP stride (uint32: half2 {p[r][2c], p[r][2c+1]})
__global__ void __launch_bounds__(1024) k_attn() {
    extern __shared__ float sm[];
    float*    qs    = sm;                        // 64*68  tf32
    float*    ks    = qs + 64 * SQ;              // 224*68 tf32 (rows 196..223 zero)
    uint32_t* vsP   = (uint32_t*)(ks + 224 * SK);// 104*72 half2 (j2 98..103 zero)
    uint32_t* psP   = vsP + 104 * SVP;           // 64*116 half2 exp(S)
    float*    rmax  = (float*)(psP + 64 * SPP);  // [8][64] warp-group partial max
    float*    rsum  = rmax + 8 * 64;             // [8][64] warp-group partial sum
    float*    maskv = rsum + 8 * 64;             // [224]

    const int t = threadIdx.x, w = t >> 5, lane = t & 31;
    const int g = lane >> 2, tq = lane & 3;
    const int nb   = blockIdx.x;
    const int head = blockIdx.y;
    const int b    = blockIdx.z;
    const int by = nb >> 4, bx = nb & 15;
    const int qoff = head * 64;
    const int pbase = b * HWH;

    // ---- mask LUT ----
    if (t < 224) {
        int j = t;
        bool valid = false;
        if (j < 196) {
            int wy = j / 14, wx = j % 14;
            int gy = by * 8 - 3 + wy, gx = bx * 8 - 3 + wx;
            valid = ((unsigned)gy < 128u) && ((unsigned)gx < 128u);
        }
        maskv[j] = valid ? 1.f : 0.f;
    }
    // ---- gather q ----
    for (int idx = t; idx < 64 * 16; idx += 1024) {
        int i = idx >> 4, d4 = (idx & 15) * 4;
        int gy = by * 8 + (i >> 3), gx = bx * 8 + (i & 7);
        float4 v = *(const float4*)&g_P[(size_t)(pbase + gy * 128 + gx) * NP + qoff + d4];
        float* d = &qs[i * SQ + d4];
        d[0] = f2tff(v.x); d[1] = f2tff(v.y); d[2] = f2tff(v.z); d[3] = f2tff(v.w);
    }
    // ---- gather k (tf32) and v (fp16 packed along j) ----
    {
        __half* vh = (__half*)vsP;
        for (int idx = t; idx < 196 * 16; idx += 1024) {
            int j = idx >> 4, d4 = (idx & 15) * 4;
            int wy = j / 14, wx = j % 14;
            int gy = by * 8 - 3 + wy, gx = bx * 8 - 3 + wx;
            bool valid = ((unsigned)gy < 128u) && ((unsigned)gx < 128u);
            float4 kv0 = make_float4(0.f, 0.f, 0.f, 0.f), kv1 = kv0;
            if (valid) {
                size_t base = (size_t)(pbase + gy * 128 + gx) * NP + 512 + qoff + d4;
                kv0 = *(const float4*)&g_P[base];
                kv1 = *(const float4*)&g_P[base + 512];
            }
            float* dk = &ks[j * SK + d4];
            dk[0] = f2tff(kv0.x); dk[1] = f2tff(kv0.y); dk[2] = f2tff(kv0.z); dk[3] = f2tff(kv0.w);
            int j2 = j >> 1, ho = j & 1;
            int hb = (j2 * SVP + d4) * 2 + ho;
            vh[hb]     = __float2half_rn(kv1.x);
            vh[hb + 2] = __float2half_rn(kv1.y);
            vh[hb + 4] = __float2half_rn(kv1.z);
            vh[hb + 6] = __float2half_rn(kv1.w);
        }
    }
    // zero pads: ks rows 196..223; vsP rows j2 98..103
    for (int idx = t; idx < 28 * SK; idx += 1024) ks[196 * SK + idx] = 0.f;
    if (t < 6 * SVP) vsP[98 * SVP + t] = 0u;
    __syncthreads();

    const int m0 = (w & 3) * 16;
    const int nq = w >> 2;                       // 0..7
    const int ntiles = nq < 4 ? 4 : 3;
    const int n0q = nq < 4 ? nq * 32 : 128 + (nq - 4) * 24;
    const int rA = m0 + g, rB = rA + 8;

    // ---- S = q @ k^T (tf32) ----
    float sacc[4][4];
    #pragma unroll
    for (int nt = 0; nt < 4; nt++)
        #pragma unroll
        for (int e = 0; e < 4; e++) sacc[nt][e] = 0.f;

    #pragma unroll
    for (int ks8 = 0; ks8 < 8; ks8++) {
        const int k0 = ks8 * 8;
        uint32_t a0 = __float_as_uint(qs[(m0 + g) * SQ + k0 + tq]);
        uint32_t a1 = __float_as_uint(qs[(m0 + g + 8) * SQ + k0 + tq]);
        uint32_t a2 = __float_as_uint(qs[(m0 + g) * SQ + k0 + tq + 4]);
        uint32_t a3 = __float_as_uint(qs[(m0 + g + 8) * SQ + k0 + tq + 4]);
        #pragma unroll
        for (int nt = 0; nt < 4; nt++) {
            if (nt < ntiles) {
                int n = n0q + nt * 8 + g;
                uint32_t b0 = __float_as_uint(ks[n * SK + k0 + tq]);
                uint32_t b1 = __float_as_uint(ks[n * SK + k0 + tq + 4]);
                mma8(sacc[nt], a0, a1, a2, a3, b0, b1);
            }
        }
    }

    // ---- mask + warp-local row max (quad shuffle) ----
    float mA = MAXNEG, mB = MAXNEG;
    #pragma unroll
    for (int nt = 0; nt < 4; nt++) {
        if (nt < ntiles) {
            int jA = n0q + nt * 8 + tq * 2, jB = jA + 1;
            bool vA = maskv[jA] != 0.f, vB = maskv[jB] != 0.f;
            sacc[nt][0] = vA ? sacc[nt][0] : MAXNEG;
            sacc[nt][1] = vB ? sacc[nt][1] : MAXNEG;
            sacc[nt][2] = vA ? sacc[nt][2] : MAXNEG;
            sacc[nt][3] = vB ? sacc[nt][3] : MAXNEG;
            mA = fmaxf(mA, fmaxf(sacc[nt][0], sacc[nt][1]));
            mB = fmaxf(mB, fmaxf(sacc[nt][2], sacc[nt][3]));
        }
    }
    mA = fmaxf(mA, __shfl_xor_sync(0xffffffffu, mA, 1));
    mA = fmaxf(mA, __shfl_xor_sync(0xffffffffu, mA, 2));
    mB = fmaxf(mB, __shfl_xor_sync(0xffffffffu, mB, 1));
    mB = fmaxf(mB, __shfl_xor_sync(0xffffffffu, mB, 2));
    if (tq == 0) { rmax[nq * 64 + rA] = mA; rmax[nq * 64 + rB] = mB; }
    __syncthreads();

    // ---- global row max ----
    float gmA = MAXNEG, gmB = MAXNEG;
    #pragma unroll
    for (int q = 0; q < 8; q++) {
        gmA = fmaxf(gmA, rmax[q * 64 + rA]);
        gmB = fmaxf(gmB, rmax[q * 64 + rB]);
    }

    // ---- exp (register) -> packed fp16 P store + partial row sums ----
    float sumA = 0.f, sumB = 0.f;
    #pragma unroll
    for (int nt = 0; nt < 4; nt++) {
        if (nt < ntiles) {
            float eA0 = __expf(sacc[nt][0] - gmA), eA1 = __expf(sacc[nt][1] - gmA);
            float eB0 = __expf(sacc[nt][2] - gmB), eB1 = __expf(sacc[nt][3] - gmB);
            sumA += eA0 + eA1; sumB += eB0 + eB1;
            __half2 hA = __floats2half2_rn(eA0, eA1);
            __half2 hB = __floats2half2_rn(eB0, eB1);
            int c = (n0q >> 1) + nt * 4 + tq;
            psP[rA * SPP + c] = *(uint32_t*)&hA;
            psP[rB * SPP + c] = *(uint32_t*)&hB;
        }
    }
    sumA += __shfl_xor_sync(0xffffffffu, sumA, 1);
    sumA += __shfl_xor_sync(0xffffffffu, sumA, 2);
    sumB += __shfl_xor_sync(0xffffffffu, sumB, 1);
    sumB += __shfl_xor_sync(0xffffffffu, sumB, 2);
    if (tq == 0) { rsum[nq * 64 + rA] = sumA; rsum[nq * 64 + rB] = sumB; }
    __syncthreads();

    // ---- O = P @ V (f16 m16n8k16), 16 warps: 4m x 4n(16 cols) ----
    if (w < 16) {
        const int m0o = (w & 3) * 16;
        const int n0o = (w >> 2) * 16;
        const int rA2 = m0o + g, rB2 = rA2 + 8;
        float oacc[2][4];
        #pragma unroll
        for (int nt = 0; nt < 2; nt++)
            #pragma unroll
            for (int e = 0; e < 4; e++) oacc[nt][e] = 0.f;

        #pragma unroll
        for (int k13 = 0; k13 < 13; k13++) {
            const int k2 = k13 * 8;
            uint32_t a0 = psP[rA2 * SPP + k2 + tq];
            uint32_t a1 = psP[rB2 * SPP + k2 + tq];
            uint32_t a2 = psP[rA2 * SPP + k2 + 4 + tq];
            uint32_t a3 = psP[rB2 * SPP + k2 + 4 + tq];
            #pragma unroll
            for (int nt = 0; nt < 2; nt++) {
                int n = n0o + nt * 8 + g;
                uint32_t b0 = vsP[(k2 + tq) * SVP + n];
                uint32_t b1 = vsP[(k2 + 4 + tq) * SVP + n];
                mma16h(oacc[nt], a0, a1, a2, a3, b0, b1);
            }
        }
        // epilogue: 1/rowsum + scatter
        float sA = 0.f, sB = 0.f;
        #pragma unroll
        for (int q = 0; q < 8; q++) {
            sA += rsum[q * 64 + rA2];
            sB += rsum[q * 64 + rB2];
        }
        float invA = 1.0f / sA, invB = 1.0f / sB;
        const int gyA = by * 8 + (rA2 >> 3), gxA = bx * 8 + (rA2 & 7);
        const int gyB = by * 8 + (rB2 >> 3), gxB = bx * 8 + (rB2 & 7);
        float* dstA = &g_AO[(size_t)(pbase + gyA * 128 + gxA) * INNER + qoff];
        float* dstB = &g_AO[(size_t)(pbase + gyB * 128 + gxB) * INNER + qoff];
        #pragma unroll
        for (int nt = 0; nt < 2; nt++) {
            int n = n0o + nt * 8 + tq * 2;
            *(float2*)&dstA[n] = make_float2(oacc[nt][0] * invA, oacc[nt][1] * invA);
            *(float2*)&dstB[n] = make_float2(oacc[nt][2] * invB, oacc[nt][3] * invB);
        }
    }
}

// ---------------------------------------------------------------------------
// Kernel 3: out = AO @ Wo + bo, transposed store. TF32 MMA. (unchanged)
// ---------------------------------------------------------------------------
#define SA3 68
#define SB3 136
__global__ void __launch_bounds__(256) k_out(const float* __restrict__ Wo,
                                             const float* __restrict__ bo,
                                             float* __restrict__ out) {
    extern __shared__ float sm[];
    float* As = sm;
    float* Bs = sm + 128 * SA3;

    const int t = threadIdx.x, w = t >> 5, lane = t & 31;
    const int g = lane >> 2, tq = lane & 3;
    const int m0w = (w & 1) * 64, n0w = (w >> 1) * 32;
    const int p0 = blockIdx.x * 128;
    const int b  = p0 >> 14;
    const int y  = (p0 & (HWH - 1)) >> 7;

    float acc[4][4][4];
    #pragma unroll
    for (int mt = 0; mt < 4; mt++)
        #pragma unroll
        for (int nt = 0; nt < 4; nt++)
            #pragma unroll
            for (int e = 0; e < 4; e++) acc[mt][nt][e] = 0.f;

    for (int kc = 0; kc < 8; kc++) {
        const int K0 = kc * 64;
        __syncthreads();
        for (int idx = t; idx < 128 * 16; idx += 256) {
            int m = idx >> 4, k4 = (idx & 15) * 4;
            float4 v = *(const float4*)&g_AO[(size_t)(p0 + m) * INNER + K0 + k4];
            float* d = &As[m * SA3 + k4];
            d[0] = f2tff(v.x); d[1] = f2tff(v.y); d[2] = f2tff(v.z); d[3] = f2tff(v.w);
        }
        for (int idx = t; idx < 64 * 32; idx += 256) {
            int k = idx >> 5, n4 = (idx & 31) * 4;
            float4 v = *(const float4*)&Wo[(size_t)(K0 + k) * CC + n4];
            float* d = &Bs[k * SB3 + n4];
            d[0] = f2tff(v.x); d[1] = f2tff(v.y); d[2] = f2tff(v.z); d[3] = f2tff(v.w);
        }
        __syncthreads();

        #pragma unroll
        for (int ks8 = 0; ks8 < 8; ks8++) {
            const int k0 = ks8 * 8;
            uint32_t af[4][4];
            #pragma unroll
            for (int mt = 0; mt < 4; mt++) {
                int m = m0w + mt * 16 + g;
                af[mt][0] = __float_as_uint(As[m * SA3 + k0 + tq]);
                af[mt][1] = __float_as_uint(As[(m + 8) * SA3 + k0 + tq]);
                af[mt][2] = __float_as_uint(As[m * SA3 + k0 + tq + 4]);
                af[mt][3] = __float_as_uint(As[(m + 8) * SA3 + k0 + tq + 4]);
            }
            #pragma unroll
            for (int nt = 0; nt < 4; nt++) {
                int n = n0w + nt * 8 + g;
                uint32_t b0 = __float_as_uint(Bs[(k0 + tq) * SB3 + n]);
                uint32_t b1 = __float_as_uint(Bs[(k0 + tq + 4) * SB3 + n]);
                #pragma unroll
                for (int mt = 0; mt < 4; mt++)
                    mma8(acc[mt][nt], af[mt][0], af[mt][1], af[mt][2], af[mt][3], b0, b1);
            }
        }
    }

    #pragma unroll
    for (int nt = 0; nt < 4; nt++) {
        int nA = n0w + nt * 8 + tq * 2, nB = nA + 1;
        float biasA = bo[nA], biasB = bo[nB];
        float* colA = out + (size_t)(b * CC + nA) * HWH + y * 128;
        float* colB = out + (size_t)(b * CC + nB) * HWH + y * 128;
        #pragma unroll
        for (int mt = 0; mt < 4; mt++) {
            int m = m0w + mt * 16 + g;
            colA[m]     = acc[mt][nt][0] + biasA;
            colB[m]     = acc[mt][nt][1] + biasB;
            colA[m + 8] = acc[mt][nt][2] + biasA;
            colB[m + 8] = acc[mt][nt][3] + biasB;
        }
    }
}

extern "C" void kernel_launch(void* const* d_in, const int* in_sizes, int n_in,
                              void* d_out, int out_size) {
    const float* x   = (const float*)d_in[0];
    const float* Wq  = (const float*)d_in[1];
    const float* Wkv = (const float*)d_in[2];
    const float* Wo  = (const float*)d_in[3];
    const float* bo  = (const float*)d_in[4];
    float* out = (float*)d_out;

    const int smem1 = 2 * 64 * S1 * 4;                              // 69632
    const int smem2 = (64 * SQ + 224 * SK + 104 * SVP + 64 * SPP
                       + 8 * 64 * 2 + 224) * 4;                     // 142976
    const int smem3 = (128 * SA3 + 64 * SB3) * 4;                   // 69632

    cudaFuncSetAttribute(k_proj, cudaFuncAttributeMaxDynamicSharedMemorySize, smem1);
    cudaFuncSetAttribute(k_attn, cudaFuncAttributeMaxDynamicSharedMemorySize, smem2);
    cudaFuncSetAttribute(k_out,  cudaFuncAttributeMaxDynamicSharedMemorySize, smem3);

    dim3 g1(12, 512);
    k_proj<<<g1, 256, smem1>>>(x, Wq, Wkv);

    dim3 g2(256, 8, 4);
    k_attn<<<g2, 1024, smem2>>>();

    dim3 g3(512);
    k_out<<<g3, 256, smem3>>>(Wo, bo, out);
}

// round 8
// speedup vs baseline: 3.9481x; 1.2463x over previous
#include <cuda_runtime.h>
#include <cuda_fp16.h>
#include <stdint.h>
#include <math.h>

#define BB 4
#define CC 128
#define HWH 16384
#define NPIX 65536
#define INNER 512
#define NP 1536
#define MAXNEG -3.402823466e38f

// fp16 scratch (10-bit mantissa == tf32 mantissa; like-for-like rounding)
__device__ __half g_Ph[(size_t)NPIX * NP];     // [q(512, pre-scaled) | k(512) | v(512)]
__device__ __half g_AOh[(size_t)NPIX * INNER];

__device__ __forceinline__ uint32_t f2tf(float f) {
    uint32_t u; asm("cvt.rna.tf32.f32 %0, %1;" : "=r"(u) : "f"(f)); return u;
}
__device__ __forceinline__ float f2tff(float f) { return __uint_as_float(f2tf(f)); }

__device__ __forceinline__ void mma8(float* c,
                                     uint32_t a0, uint32_t a1, uint32_t a2, uint32_t a3,
                                     uint32_t b0, uint32_t b1) {
    asm volatile("mma.sync.aligned.m16n8k8.row.col.f32.tf32.tf32.f32 "
        "{%0,%1,%2,%3}, {%4,%5,%6,%7}, {%8,%9}, {%0,%1,%2,%3};"
        : "+f"(c[0]), "+f"(c[1]), "+f"(c[2]), "+f"(c[3])
        : "r"(a0), "r"(a1), "r"(a2), "r"(a3), "r"(b0), "r"(b1));
}
__device__ __forceinline__ void mma16h(float* c,
                                       uint32_t a0, uint32_t a1, uint32_t a2, uint32_t a3,
                                       uint32_t b0, uint32_t b1) {
    asm volatile("mma.sync.aligned.m16n8k16.row.col.f32.f16.f16.f32 "
        "{%0,%1,%2,%3}, {%4,%5,%6,%7}, {%8,%9}, {%0,%1,%2,%3};"
        : "+f"(c[0]), "+f"(c[1]), "+f"(c[2]), "+f"(c[3])
        : "r"(a0), "r"(a1), "r"(a2), "r"(a3), "r"(b0), "r"(b1));
}

// ---------------------------------------------------------------------------
// Kernel 1: P[p,:] = x_pixel[p,:] @ [Wq*0.125 | Wkv].  TF32 MMA, fp16 store.
// ---------------------------------------------------------------------------
#define S1 136
__global__ void __launch_bounds__(256) k_proj(const float* __restrict__ x,
                                              const float* __restrict__ Wq,
                                              const float* __restrict__ Wkv) {
    extern __shared__ float sm[];
    float* As = sm;
    float* Bs = sm + 64 * S1;

    const int t = threadIdx.x, w = t >> 5, lane = t & 31;
    const int g = lane >> 2, tq = lane & 3;
    const int m0w = (w & 1) * 64, n0w = (w >> 1) * 32;
    const int jt = blockIdx.x;
    const int p0 = blockIdx.y * 128;
    const int b  = p0 >> 14;
    const int y  = (p0 & (HWH - 1)) >> 7;

    float acc[4][4][4];
    #pragma unroll
    for (int mt = 0; mt < 4; mt++)
        #pragma unroll
        for (int nt = 0; nt < 4; nt++)
            #pragma unroll
            for (int e = 0; e < 4; e++) acc[mt][nt][e] = 0.f;

    for (int kc = 0; kc < 2; kc++) {
        const int K0 = kc * 64;
        __syncthreads();
        const float* xb = x + ((size_t)(b * CC + K0) * 128 + y) * 128;
        for (int idx = t; idx < 64 * 32; idx += 256) {
            int k = idx >> 5, m4 = (idx & 31) * 4;
            float4 v = *(const float4*)(xb + (size_t)k * HWH + m4);
            float* d = &As[k * S1 + m4];
            d[0] = f2tff(v.x); d[1] = f2tff(v.y); d[2] = f2tff(v.z); d[3] = f2tff(v.w);
        }
        if (jt < 4) {
            const float* Wb = Wq + (size_t)K0 * INNER + jt * 128;
            for (int idx = t; idx < 64 * 32; idx += 256) {
                int k = idx >> 5, n4 = (idx & 31) * 4;
                float4 v = *(const float4*)(Wb + (size_t)k * INNER + n4);
                float* d = &Bs[k * S1 + n4];
                d[0] = f2tff(v.x * 0.125f); d[1] = f2tff(v.y * 0.125f);
                d[2] = f2tff(v.z * 0.125f); d[3] = f2tff(v.w * 0.125f);
            }
        } else {
            const float* Wb = Wkv + (size_t)K0 * 1024 + (jt - 4) * 128;
            for (int idx = t; idx < 64 * 32; idx += 256) {
                int k = idx >> 5, n4 = (idx & 31) * 4;
                float4 v = *(const float4*)(Wb + (size_t)k * 1024 + n4);
                float* d = &Bs[k * S1 + n4];
                d[0] = f2tff(v.x); d[1] = f2tff(v.y); d[2] = f2tff(v.z); d[3] = f2tff(v.w);
            }
        }
        __syncthreads();

        #pragma unroll
        for (int ks = 0; ks < 8; ks++) {
            const int k0 = ks * 8;
            uint32_t af[4][4];
            #pragma unroll
            for (int mt = 0; mt < 4; mt++) {
                int m = m0w + mt * 16 + g;
                af[mt][0] = __float_as_uint(As[(k0 + tq) * S1 + m]);
                af[mt][1] = __float_as_uint(As[(k0 + tq) * S1 + m + 8]);
                af[mt][2] = __float_as_uint(As[(k0 + tq + 4) * S1 + m]);
                af[mt][3] = __float_as_uint(As[(k0 + tq + 4) * S1 + m + 8]);
            }
            #pragma unroll
            for (int nt = 0; nt < 4; nt++) {
                int n = n0w + nt * 8 + g;
                uint32_t b0 = __float_as_uint(Bs[(k0 + tq) * S1 + n]);
                uint32_t b1 = __float_as_uint(Bs[(k0 + tq + 4) * S1 + n]);
                #pragma unroll
                for (int mt = 0; mt < 4; mt++)
                    mma8(acc[mt][nt], af[mt][0], af[mt][1], af[mt][2], af[mt][3], b0, b1);
            }
        }
    }

    const int colb = jt * 128;
    #pragma unroll
    for (int mt = 0; mt < 4; mt++) {
        int m = m0w + mt * 16 + g;
        #pragma unroll
        for (int nt = 0; nt < 4; nt++) {
            int n = colb + n0w + nt * 8 + tq * 2;
            *(__half2*)&g_Ph[(size_t)(p0 + m) * NP + n]     = __floats2half2_rn(acc[mt][nt][0], acc[mt][nt][1]);
            *(__half2*)&g_Ph[(size_t)(p0 + m + 8) * NP + n] = __floats2half2_rn(acc[mt][nt][2], acc[mt][nt][3]);
        }
    }
}

// ---------------------------------------------------------------------------
// Kernel 2: halo attention. 1024 threads = 32 warps. All-f16 MMA (fp32 accum).
// S: m16n8k16, q/k packed half2 along d. Register softmax. O: m16n8k16.
// smem (uint32): qsP[64][36] ksP[224][36] vsP[104][72] psP[64][116]
//                rmax[8][64] rsum[8][64] maskv[224]
// ---------------------------------------------------------------------------
#define SQP 36
#define SKP 36
#define SVP 72
#define SPP 116
__global__ void __launch_bounds__(1024) k_attn() {
    extern __shared__ uint32_t smu[];
    uint32_t* qsP   = smu;                       // 64*36
    uint32_t* ksP   = qsP + 64 * SQP;            // 224*36 (rows 196..223 zero)
    uint32_t* vsP   = ksP + 224 * SKP;           // 104*72 (j2 98..103 zero)
    uint32_t* psP   = vsP + 104 * SVP;           // 64*116
    float*    rmax  = (float*)(psP + 64 * SPP);  // [8][64]
    float*    rsum  = rmax + 8 * 64;             // [8][64]
    float*    maskv = rsum + 8 * 64;             // [224]

    const int t = threadIdx.x, w = t >> 5, lane = t & 31;
    const int g = lane >> 2, tq = lane & 3;
    const int nb   = blockIdx.x;
    const int head = blockIdx.y;
    const int b    = blockIdx.z;
    const int by = nb >> 4, bx = nb & 15;
    const int qoff = head * 64;
    const int pbase = b * HWH;

    // ---- mask LUT ----
    if (t < 224) {
        int j = t;
        bool valid = false;
        if (j < 196) {
            int wy = j / 14, wx = j % 14;
            int gy = by * 8 - 3 + wy, gx = bx * 8 - 3 + wx;
            valid = ((unsigned)gy < 128u) && ((unsigned)gx < 128u);
        }
        maskv[j] = valid ? 1.f : 0.f;
    }
    // ---- gather q (fp16, packed half2 along d) ----
    for (int idx = t; idx < 64 * 16; idx += 1024) {
        int i = idx >> 4, d4 = (idx & 15) * 4;
        int gy = by * 8 + (i >> 3), gx = bx * 8 + (i & 7);
        uint2 v = *(const uint2*)&g_Ph[(size_t)(pbase + gy * 128 + gx) * NP + qoff + d4];
        qsP[i * SQP + (d4 >> 1)]     = v.x;
        qsP[i * SQP + (d4 >> 1) + 1] = v.y;
    }
    // ---- gather k (packed along d) and v (packed along j) ----
    {
        __half* vh = (__half*)vsP;
        for (int idx = t; idx < 196 * 16; idx += 1024) {
            int j = idx >> 4, d4 = (idx & 15) * 4;
            int wy = j / 14, wx = j % 14;
            int gy = by * 8 - 3 + wy, gx = bx * 8 - 3 + wx;
            bool valid = ((unsigned)gy < 128u) && ((unsigned)gx < 128u);
            uint2 kv0 = make_uint2(0u, 0u), kv1 = kv0;
            if (valid) {
                size_t base = (size_t)(pbase + gy * 128 + gx) * NP + 512 + qoff + d4;
                kv0 = *(const uint2*)&g_Ph[base];
                kv1 = *(const uint2*)&g_Ph[base + 512];
            }
            ksP[j * SKP + (d4 >> 1)]     = kv0.x;
            ksP[j * SKP + (d4 >> 1) + 1] = kv0.y;
            const __half* pv = (const __half*)&kv1;
            int j2 = j >> 1, ho = j & 1;
            int hb = (j2 * SVP + d4) * 2 + ho;
            vh[hb]     = pv[0];
            vh[hb + 2] = pv[1];
            vh[hb + 4] = pv[2];
            vh[hb + 6] = pv[3];
        }
    }
    // zero pads: ksP rows 196..223; vsP rows j2 98..103
    for (int idx = t; idx < 28 * SKP; idx += 1024) ksP[196 * SKP + idx] = 0u;
    if (t < 6 * SVP) vsP[98 * SVP + t] = 0u;
    __syncthreads();

    const int m0 = (w & 3) * 16;
    const int nq = w >> 2;                       // 0..7
    const int ntiles = nq < 4 ? 4 : 3;
    const int n0q = nq < 4 ? nq * 32 : 128 + (nq - 4) * 24;
    const int rA = m0 + g, rB = rA + 8;

    // ---- S = q @ k^T (f16 m16n8k16, K=64 in 4 steps) ----
    float sacc[4][4];
    #pragma unroll
    for (int nt = 0; nt < 4; nt++)
        #pragma unroll
        for (int e = 0; e < 4; e++) sacc[nt][e] = 0.f;

    #pragma unroll
    for (int ks16 = 0; ks16 < 4; ks16++) {
        const int k8 = ks16 * 8;
        uint32_t a0 = qsP[rA * SQP + k8 + tq];
        uint32_t a1 = qsP[rB * SQP + k8 + tq];
        uint32_t a2 = qsP[rA * SQP + k8 + tq + 4];
        uint32_t a3 = qsP[rB * SQP + k8 + tq + 4];
        #pragma unroll
        for (int nt = 0; nt < 4; nt++) {
            if (nt < ntiles) {
                int n = n0q + nt * 8 + g;
                uint32_t b0 = ksP[n * SKP + k8 + tq];
                uint32_t b1 = ksP[n * SKP + k8 + tq + 4];
                mma16h(sacc[nt], a0, a1, a2, a3, b0, b1);
            }
        }
    }

    // ---- mask + warp-local row max ----
    float mA = MAXNEG, mB = MAXNEG;
    #pragma unroll
    for (int nt = 0; nt < 4; nt++) {
        if (nt < ntiles) {
            int jA = n0q + nt * 8 + tq * 2, jB = jA + 1;
            bool vA = maskv[jA] != 0.f, vB = maskv[jB] != 0.f;
            sacc[nt][0] = vA ? sacc[nt][0] : MAXNEG;
            sacc[nt][1] = vB ? sacc[nt][1] : MAXNEG;
            sacc[nt][2] = vA ? sacc[nt][2] : MAXNEG;
            sacc[nt][3] = vB ? sacc[nt][3] : MAXNEG;
            mA = fmaxf(mA, fmaxf(sacc[nt][0], sacc[nt][1]));
            mB = fmaxf(mB, fmaxf(sacc[nt][2], sacc[nt][3]));
        }
    }
    mA = fmaxf(mA, __shfl_xor_sync(0xffffffffu, mA, 1));
    mA = fmaxf(mA, __shfl_xor_sync(0xffffffffu, mA, 2));
    mB = fmaxf(mB, __shfl_xor_sync(0xffffffffu, mB, 1));
    mB = fmaxf(mB, __shfl_xor_sync(0xffffffffu, mB, 2));
    if (tq == 0) { rmax[nq * 64 + rA] = mA; rmax[nq * 64 + rB] = mB; }
    __syncthreads();

    float gmA = MAXNEG, gmB = MAXNEG;
    #pragma unroll
    for (int q = 0; q < 8; q++) {
        gmA = fmaxf(gmA, rmax[q * 64 + rA]);
        gmB = fmaxf(gmB, rmax[q * 64 + rB]);
    }

    // ---- exp -> packed fp16 P + partial row sums ----
    float sumA = 0.f, sumB = 0.f;
    #pragma unroll
    for (int nt = 0; nt < 4; nt++) {
        if (nt < ntiles) {
            float eA0 = __expf(sacc[nt][0] - gmA), eA1 = __expf(sacc[nt][1] - gmA);
            float eB0 = __expf(sacc[nt][2] - gmB), eB1 = __expf(sacc[nt][3] - gmB);
            sumA += eA0 + eA1; sumB += eB0 + eB1;
            __half2 hA = __floats2half2_rn(eA0, eA1);
            __half2 hB = __floats2half2_rn(eB0, eB1);
            int c = (n0q >> 1) + nt * 4 + tq;
            psP[rA * SPP + c] = *(uint32_t*)&hA;
            psP[rB * SPP + c] = *(uint32_t*)&hB;
        }
    }
    sumA += __shfl_xor_sync(0xffffffffu, sumA, 1);
    sumA += __shfl_xor_sync(0xffffffffu, sumA, 2);
    sumB += __shfl_xor_sync(0xffffffffu, sumB, 1);
    sumB += __shfl_xor_sync(0xffffffffu, sumB, 2);
    if (tq == 0) { rsum[nq * 64 + rA] = sumA; rsum[nq * 64 + rB] = sumB; }
    __syncthreads();

    // ---- O = P @ V (f16 m16n8k16), 16 warps: 4m x 4n(16 cols) ----
    if (w < 16) {
        const int m0o = (w & 3) * 16;
        const int n0o = (w >> 2) * 16;
        const int rA2 = m0o + g, rB2 = rA2 + 8;
        float oacc[2][4];
        #pragma unroll
        for (int nt = 0; nt < 2; nt++)
            #pragma unroll
            for (int e = 0; e < 4; e++) oacc[nt][e] = 0.f;

        #pragma unroll
        for (int k13 = 0; k13 < 13; k13++) {
            const int k2 = k13 * 8;
            uint32_t a0 = psP[rA2 * SPP + k2 + tq];
            uint32_t a1 = psP[rB2 * SPP + k2 + tq];
            uint32_t a2 = psP[rA2 * SPP + k2 + 4 + tq];
            uint32_t a3 = psP[rB2 * SPP + k2 + 4 + tq];
            #pragma unroll
            for (int nt = 0; nt < 2; nt++) {
                int n = n0o + nt * 8 + g;
                uint32_t b0 = vsP[(k2 + tq) * SVP + n];
                uint32_t b1 = vsP[(k2 + 4 + tq) * SVP + n];
                mma16h(oacc[nt], a0, a1, a2, a3, b0, b1);
            }
        }
        float sA = 0.f, sB = 0.f;
        #pragma unroll
        for (int q = 0; q < 8; q++) {
            sA += rsum[q * 64 + rA2];
            sB += rsum[q * 64 + rB2];
        }
        float invA = 1.0f / sA, invB = 1.0f / sB;
        const int gyA = by * 8 + (rA2 >> 3), gxA = bx * 8 + (rA2 & 7);
        const int gyB = by * 8 + (rB2 >> 3), gxB = bx * 8 + (rB2 & 7);
        __half* dstA = &g_AOh[(size_t)(pbase + gyA * 128 + gxA) * INNER + qoff];
        __half* dstB = &g_AOh[(size_t)(pbase + gyB * 128 + gxB) * INNER + qoff];
        #pragma unroll
        for (int nt = 0; nt < 2; nt++) {
            int n = n0o + nt * 8 + tq * 2;
            *(__half2*)&dstA[n] = __floats2half2_rn(oacc[nt][0] * invA, oacc[nt][1] * invA);
            *(__half2*)&dstB[n] = __floats2half2_rn(oacc[nt][2] * invB, oacc[nt][3] * invB);
        }
    }
}

// ---------------------------------------------------------------------------
// Kernel 3: out = AO(fp16) @ Wo + bo, transposed store. TF32 MMA.
// ---------------------------------------------------------------------------
#define SA3 68
#define SB3 136
__global__ void __launch_bounds__(256) k_out(const float* __restrict__ Wo,
                                             const float* __restrict__ bo,
                                             float* __restrict__ out) {
    extern __shared__ float sm[];
    float* As = sm;
    float* Bs = sm + 128 * SA3;

    const int t = threadIdx.x, w = t >> 5, lane = t & 31;
    const int g = lane >> 2, tq = lane & 3;
    const int m0w = (w & 1) * 64, n0w = (w >> 1) * 32;
    const int p0 = blockIdx.x * 128;
    const int b  = p0 >> 14;
    const int y  = (p0 & (HWH - 1)) >> 7;

    float acc[4][4][4];
    #pragma unroll
    for (int mt = 0; mt < 4; mt++)
        #pragma unroll
        for (int nt = 0; nt < 4; nt++)
            #pragma unroll
            for (int e = 0; e < 4; e++) acc[mt][nt][e] = 0.f;

    for (int kc = 0; kc < 8; kc++) {
        const int K0 = kc * 64;
        __syncthreads();
        for (int idx = t; idx < 128 * 16; idx += 256) {
            int m = idx >> 4, k4 = (idx & 15) * 4;
            uint2 v = *(const uint2*)&g_AOh[(size_t)(p0 + m) * INNER + K0 + k4];
            const __half* ph = (const __half*)&v;
            float* d = &As[m * SA3 + k4];
            d[0] = f2tff(__half2float(ph[0]));
            d[1] = f2tff(__half2float(ph[1]));
            d[2] = f2tff(__half2float(ph[2]));
            d[3] = f2tff(__half2float(ph[3]));
        }
        for (int idx = t; idx < 64 * 32; idx += 256) {
            int k = idx >> 5, n4 = (idx & 31) * 4;
            float4 v = *(const float4*)&Wo[(size_t)(K0 + k) * CC + n4];
            float* d = &Bs[k * SB3 + n4];
            d[0] = f2tff(v.x); d[1] = f2tff(v.y); d[2] = f2tff(v.z); d[3] = f2tff(v.w);
        }
        __syncthreads();

        #pragma unroll
        for (int ks8 = 0; ks8 < 8; ks8++) {
            const int k0 = ks8 * 8;
            uint32_t af[4][4];
            #pragma unroll
            for (int mt = 0; mt < 4; mt++) {
                int m = m0w + mt * 16 + g;
                af[mt][0] = __float_as_uint(As[m * SA3 + k0 + tq]);
                af[mt][1] = __float_as_uint(As[(m + 8) * SA3 + k0 + tq]);
                af[mt][2] = __float_as_uint(As[m * SA3 + k0 + tq + 4]);
                af[mt][3] = __float_as_uint(As[(m + 8) * SA3 + k0 + tq + 4]);
            }
            #pragma unroll
            for (int nt = 0; nt < 4; nt++) {
                int n = n0w + nt * 8 + g;
                uint32_t b0 = __float_as_uint(Bs[(k0 + tq) * SB3 + n]);
                uint32_t b1 = __float_as_uint(Bs[(k0 + tq + 4) * SB3 + n]);
                #pragma unroll
                for (int mt = 0; mt < 4; mt++)
                    mma8(acc[mt][nt], af[mt][0], af[mt][1], af[mt][2], af[mt][3], b0, b1);
            }
        }
    }

    #pragma unroll
    for (int nt = 0; nt < 4; nt++) {
        int nA = n0w + nt * 8 + tq * 2, nB = nA + 1;
        float biasA = bo[nA], biasB = bo[nB];
        float* colA = out + (size_t)(b * CC + nA) * HWH + y * 128;
        float* colB = out + (size_t)(b * CC + nB) * HWH + y * 128;
        #pragma unroll
        for (int mt = 0; mt < 4; mt++) {
            int m = m0w + mt * 16 + g;
            colA[m]     = acc[mt][nt][0] + biasA;
            colB[m]     = acc[mt][nt][1] + biasB;
            colA[m + 8] = acc[mt][nt][2] + biasA;
            colB[m + 8] = acc[mt][nt][3] + biasB;
        }
    }
}

extern "C" void kernel_launch(void* const* d_in, const int* in_sizes, int n_in,
                              void* d_out, int out_size) {
    const float* x   = (const float*)d_in[0];
    const float* Wq  = (const float*)d_in[1];
    const float* Wkv = (const float*)d_in[2];
    const float* Wo  = (const float*)d_in[3];
    const float* bo  = (const float*)d_in[4];
    float* out = (float*)d_out;

    const int smem1 = 2 * 64 * S1 * 4;                                   // 69632
    const int smem2 = (64 * SQP + 224 * SKP + 104 * SVP + 64 * SPP
                       + 8 * 64 * 2 + 224) * 4;                          // 106112
    const int smem3 = (128 * SA3 + 64 * SB3) * 4;                        // 69632

    cudaFuncSetAttribute(k_proj, cudaFuncAttributeMaxDynamicSharedMemorySize, smem1);
    cudaFuncSetAttribute(k_attn, cudaFuncAttributeMaxDynamicSharedMemorySize, smem2);
    cudaFuncSetAttribute(k_out,  cudaFuncAttributeMaxDynamicSharedMemorySize, smem3);

    dim3 g1(12, 512);
    k_proj<<<g1, 256, smem1>>>(x, Wq, Wkv);

    dim3 g2(256, 8, 4);
    k_attn<<<g2, 1024, smem2>>>();

    dim3 g3(512);
    k_out<<<g3, 256, smem3>>>(Wo, bo, out);
}